// round 11
// baseline (speedup 1.0000x reference)
#include <cuda_runtime.h>
#include <cuda_bf16.h>
#include <cuda_fp16.h>
#include <math_constants.h>
#include <cstdint>

#define NROI 2048
#define CDIM 1024
#define GRP  16
#define DH   64

// ============================================================================
// device scratch
// ============================================================================
__device__ __nv_bfloat16 g_A0h[NROI * CDIM], g_A0l[NROI * CDIM];   // split relu(in_x)
__device__ __nv_bfloat16 g_A1h[NROI * CDIM], g_A1l[NROI * CDIM];   // split relu(H0)
__device__ __nv_bfloat16 g_A2h[NROI * CDIM], g_A2l[NROI * CDIM];   // split in_x
__device__ __nv_bfloat16 g_W0h[CDIM * CDIM], g_W0l[CDIM * CDIM];
__device__ __nv_bfloat16 g_W1h[CDIM * CDIM], g_W1l[CDIM * CDIM];
__device__ __nv_bfloat16 g_Wph[CDIM * CDIM], g_Wpl[CDIM * CDIM];
__device__ __nv_bfloat16 g_Xh[NROI * CDIM], g_Xl[NROI * CDIM];     // embedded X (Q/K), bf16 split
__device__ __half        g_Vh[NROI * CDIM], g_Vl[NROI * CDIM];     // V, fp16 split
__device__ float g_LI[NROI * NROI];                                 // log2(iou + 1e-6)

// ============================================================================
// PTX helpers
// ============================================================================
__device__ __forceinline__ uint32_t smem_u32(const void* p) {
    uint32_t a;
    asm("{ .reg .u64 t; cvta.to.shared.u64 t, %1; cvt.u32.u64 %0, t; }" : "=r"(a) : "l"(p));
    return a;
}
#define LDSM4(r, addr) \
    asm volatile("ldmatrix.sync.aligned.m8n8.x4.shared.b16 {%0,%1,%2,%3}, [%4];" \
        : "=r"((r)[0]), "=r"((r)[1]), "=r"((r)[2]), "=r"((r)[3]) : "r"(addr))
#define LDSM4T(r, addr) \
    asm volatile("ldmatrix.sync.aligned.m8n8.x4.trans.shared.b16 {%0,%1,%2,%3}, [%4];" \
        : "=r"((r)[0]), "=r"((r)[1]), "=r"((r)[2]), "=r"((r)[3]) : "r"(addr))
#define LDSM2(r, addr) \
    asm volatile("ldmatrix.sync.aligned.m8n8.x2.shared.b16 {%0,%1}, [%2];" \
        : "=r"((r)[0]), "=r"((r)[1]) : "r"(addr))
#define MMA_BF16(c, a, b) \
    asm volatile("mma.sync.aligned.m16n8k16.row.col.f32.bf16.bf16.f32 " \
        "{%0,%1,%2,%3}, {%4,%5,%6,%7}, {%8,%9}, {%0,%1,%2,%3};" \
        : "+f"((c)[0]), "+f"((c)[1]), "+f"((c)[2]), "+f"((c)[3]) \
        : "r"((a)[0]), "r"((a)[1]), "r"((a)[2]), "r"((a)[3]), "r"((b)[0]), "r"((b)[1]))
#define MMA_F16(c, a, b) \
    asm volatile("mma.sync.aligned.m16n8k16.row.col.f32.f16.f16.f32 " \
        "{%0,%1,%2,%3}, {%4,%5,%6,%7}, {%8,%9}, {%0,%1,%2,%3};" \
        : "+f"((c)[0]), "+f"((c)[1]), "+f"((c)[2]), "+f"((c)[3]) \
        : "r"((a)[0]), "r"((a)[1]), "r"((a)[2]), "r"((a)[3]), "r"((b)[0]), "r"((b)[1]))
#define CP16(dst, src)  asm volatile("cp.async.cg.shared.global [%0], [%1], 16;" :: "r"(dst), "l"(src))
#define CP_COMMIT()     asm volatile("cp.async.commit_group;" ::: "memory")
#define CP_WAIT(n)      asm volatile("cp.async.wait_group %0;" :: "n"(n) : "memory")

__device__ __forceinline__ uint32_t bf2pk(float hi, float lo) {
    uint32_t r; asm("cvt.rn.bf16x2.f32 %0, %1, %2;" : "=r"(r) : "f"(hi), "f"(lo)); return r;
}
__device__ __forceinline__ uint32_t hf2pk(float hi, float lo) {
    uint32_t r; asm("cvt.rn.f16x2.f32 %0, %1, %2;" : "=r"(r) : "f"(hi), "f"(lo)); return r;
}
__device__ __forceinline__ float ex2f(float x) {
    float r; asm("ex2.approx.f32 %0, %1;" : "=f"(r) : "f"(x)); return r;
}

// ============================================================================
// merged split kernel (one launch, 5 segments)
// ============================================================================
__global__ __launch_bounds__(256)
void split_all(const float* __restrict__ in_x, const float* __restrict__ W0,
               const float* __restrict__ W1, const float* __restrict__ Wp,
               __nv_bfloat16* __restrict__ a0h, __nv_bfloat16* __restrict__ a0l,
               __nv_bfloat16* __restrict__ a2h, __nv_bfloat16* __restrict__ a2l,
               __nv_bfloat16* __restrict__ w0h, __nv_bfloat16* __restrict__ w0l,
               __nv_bfloat16* __restrict__ w1h, __nv_bfloat16* __restrict__ w1l,
               __nv_bfloat16* __restrict__ wph, __nv_bfloat16* __restrict__ wpl) {
    const int b = blockIdx.x;
    const float* src; __nv_bfloat16 *hi, *lo; int relu = 0, base;
    if      (b < 2048) { src = in_x; hi = a0h; lo = a0l; relu = 1; base = 0; }
    else if (b < 4096) { src = in_x; hi = a2h; lo = a2l; base = 2048; }
    else if (b < 5120) { src = W0;   hi = w0h; lo = w0l; base = 4096; }
    else if (b < 6144) { src = W1;   hi = w1h; lo = w1l; base = 5120; }
    else               { src = Wp;   hi = wph; lo = wpl; base = 6144; }
    int i = (b - base) * 256 + threadIdx.x;
    float4 v = ((const float4*)src)[i];
    if (relu) {
        v.x = fmaxf(v.x, 0.f); v.y = fmaxf(v.y, 0.f);
        v.z = fmaxf(v.z, 0.f); v.w = fmaxf(v.w, 0.f);
    }
    float f[4] = {v.x, v.y, v.z, v.w};
    uint32_t hu[2], lu[2];
    #pragma unroll
    for (int j = 0; j < 2; j++) {
        uint32_t h = bf2pk(f[2*j+1], f[2*j]);
        float e0 = __uint_as_float(h << 16);
        float e1 = __uint_as_float(h & 0xffff0000u);
        hu[j] = h;
        lu[j] = bf2pk(f[2*j+1] - e1, f[2*j] - e0);
    }
    ((uint2*)hi)[i] = make_uint2(hu[0], hu[1]);
    ((uint2*)lo)[i] = make_uint2(lu[0], lu[1]);
}

// ============================================================================
// HMMA split-bf16 GEMM, 128x64 tile, occ 2, dual-problem launch (gridDim.z)
//   mode 0: relu(acc+bias)->bf16 split   mode 1: acc+bias->bf16 split
//   mode 2: acc->fp16 split
// ============================================================================
struct GP {
    const __nv_bfloat16 *Ah, *Al, *Bh, *Bl;
    const float* bias;
    __nv_bfloat16 *oHi, *oLo;
    int mode;
};

#define A_T   10240                  // 128 rows x 80 B
#define B_T   5120                   // 64 rows x 80 B
#define STG   (2 * A_T + 2 * B_T)    // 30720
#define GEMM_SMEM (2 * STG)          // 61440

__global__ __launch_bounds__(256, 2)
void gemm_tc(GP p0, GP p1) {
    const GP p = (blockIdx.z == 0) ? p0 : p1;
    extern __shared__ char smc[];
    const uint32_t sb = smem_u32(smc);
    const int tid = threadIdx.x;
    const int wid = tid >> 5, lane = tid & 31;
    const int wm = wid & 3, wn = wid >> 2;         // 4 x 2 warp grid (32x32 tiles)
    const int row0 = blockIdx.y * 128;
    const int col0 = blockIdx.x * 64;

    auto cp_chunk = [&](int c, int s) {
        const int kb2 = c * 64;                    // K-chunk byte offset (32 cols * 2B)
        #pragma unroll
        for (int i = 0; i < 6; i++) {
            int id = tid + i * 256;
            uint32_t dst; const char* src;
            if (id < 1024) {                       // A hi/lo: 128 rows x 4 quads
                int t = id >> 9, r = (id >> 2) & 127, q = id & 3;
                src = (const char*)((t ? p.Al : p.Ah) + (size_t)(row0 + r) * CDIM)
                    + kb2 + q * 16;
                dst = sb + s * STG + t * A_T + r * 80 + q * 16;
            } else {                               // B hi/lo: 64 rows x 4 quads
                int id2 = id - 1024;
                int t = id2 >> 8, r = (id2 >> 2) & 63, q = id2 & 3;
                src = (const char*)((t ? p.Bl : p.Bh) + (size_t)(col0 + r) * CDIM)
                    + kb2 + q * 16;
                dst = sb + s * STG + 2 * A_T + t * B_T + r * 80 + q * 16;
            }
            CP16(dst, src);
        }
    };

    float acc[2][4][4] = {};
    cp_chunk(0, 0); CP_COMMIT();

    for (int c = 0; c < 32; c++) {
        const int s = c & 1;
        if (c < 31) { cp_chunk(c + 1, s ^ 1); CP_COMMIT(); CP_WAIT(1); }
        else        { CP_WAIT(0); }
        __syncthreads();

        const uint32_t stg = sb + s * STG;
        #pragma unroll
        for (int ks = 0; ks < 2; ks++) {
            uint32_t ah[2][4], al[2][4], bh[4][2], bl[4][2];
            {
                const int kk = ks * 16 + (lane >> 4) * 8;
                #pragma unroll
                for (int mt = 0; mt < 2; mt++) {
                    uint32_t ad = stg + (wm * 32 + mt * 16 + (lane & 15)) * 80 + kk * 2;
                    LDSM4(ah[mt], ad);
                    LDSM4(al[mt], ad + A_T);
                }
            }
            {
                const int kk = ks * 16 + ((lane >> 3) & 1) * 8;
                #pragma unroll
                for (int nt = 0; nt < 4; nt++) {
                    uint32_t bd = stg + 2 * A_T + (wn * 32 + nt * 8 + (lane & 7)) * 80 + kk * 2;
                    LDSM2(bh[nt], bd);
                    LDSM2(bl[nt], bd + B_T);
                }
            }
            #pragma unroll
            for (int mt = 0; mt < 2; mt++)
                #pragma unroll
                for (int nt = 0; nt < 4; nt++) {
                    MMA_BF16(acc[mt][nt], ah[mt], bh[nt]);
                    MMA_BF16(acc[mt][nt], ah[mt], bl[nt]);
                    MMA_BF16(acc[mt][nt], al[mt], bh[nt]);
                }
        }
        __syncthreads();
    }

    const int g = lane >> 2, th = lane & 3;
    #pragma unroll
    for (int mt = 0; mt < 2; mt++)
        #pragma unroll
        for (int nt = 0; nt < 4; nt++) {
            const int row = row0 + wm * 32 + mt * 16 + g;
            const int col = col0 + wn * 32 + nt * 8 + th * 2;
            float2 bv = make_float2(0.f, 0.f);
            if (p.mode != 2) bv = *(const float2*)(p.bias + col);
            const float* cc = acc[mt][nt];
            #pragma unroll
            for (int h = 0; h < 2; h++) {
                float v0 = cc[h * 2 + 0] + bv.x;
                float v1 = cc[h * 2 + 1] + bv.y;
                if (p.mode == 0) { v0 = fmaxf(v0, 0.f); v1 = fmaxf(v1, 0.f); }
                size_t o = (size_t)(row + h * 8) * CDIM + col;
                if (p.mode == 2) {
                    uint32_t hp = hf2pk(v1, v0);
                    __half2 hh = *(__half2*)&hp;
                    float2 e = __half22float2(hh);
                    *(uint32_t*)(p.oHi + o) = hp;
                    *(uint32_t*)(p.oLo + o) = hf2pk(v1 - e.y, v0 - e.x);
                } else {
                    uint32_t hp = bf2pk(v1, v0);
                    float e0 = __uint_as_float(hp << 16);
                    float e1 = __uint_as_float(hp & 0xffff0000u);
                    *(uint32_t*)(p.oHi + o) = hp;
                    *(uint32_t*)(p.oLo + o) = bf2pk(v1 - e1, v0 - e0);
                }
            }
        }
}

// ============================================================================
// log2(IoU + 1e-6) table
// ============================================================================
__global__ __launch_bounds__(256)
void logiou_kernel(const float* __restrict__ rois, float* __restrict__ li) {
    int idx = blockIdx.x * blockDim.x + threadIdx.x;
    int n = idx >> 11;
    int m = idx & 2047;
    const float* a = rois + n * 5 + 1;
    const float* b = rois + m * 5 + 1;
    float ax1 = a[0], ay1 = a[1], ax2 = a[2], ay2 = a[3];
    float bx1 = b[0], by1 = b[1], bx2 = b[2], by2 = b[3];
    float areaA = (ax2 - ax1 + 1.f) * (ay2 - ay1 + 1.f);
    float areaB = (bx2 - bx1 + 1.f) * (by2 - by1 + 1.f);
    float w = fminf(ax2, bx2) - fmaxf(ax1, bx1) + 1.f; w = fmaxf(w, 0.f);
    float h = fminf(ay2, by2) - fmaxf(ay1, by1) + 1.f; h = fmaxf(h, 0.f);
    float inter = w * h;
    float iou = __fdividef(inter, areaA + areaB - inter);
    li[idx] = __log2f(iou + 1e-6f);
}

// ============================================================================
// HMMA flash attention, occ 2 (Q staged through KV double buffer; 72KB smem)
// ============================================================================
#define FP 144
#define SOFF(s, t)  ((s) * (4 * 64 * FP) + (t) * (64 * FP))
#define FLASH_SMEM  (2 * 4 * 64 * FP)            // 73728 B
#define SCL8_LOG2E  0.1803368801111204f          // 0.125 * log2(e)

__global__ __launch_bounds__(256, 2)
void flash_hmma(const __nv_bfloat16* __restrict__ Xh, const __nv_bfloat16* __restrict__ Xl,
                const __nv_bfloat16* __restrict__ Vh, const __nv_bfloat16* __restrict__ Vl,
                const float* __restrict__ LI, const float* __restrict__ bout,
                float* __restrict__ out) {
    extern __shared__ char smc[];
    const uint32_t sb = smem_u32(smc);
    const int tid = threadIdx.x;
    const int wid = tid >> 5, lane = tid & 31;
    const int g = lane >> 2, th = lane & 3;
    const int n0 = blockIdx.x * 128;
    const int grp = blockIdx.y;
    const size_t gcol = (size_t)grp * DH;

    const __nv_bfloat16* kvsrc[4] = {Xh, Xl, Vh, Vl};

    auto cp_kv = [&](int it, int s) {
        const int m0 = it * 64;
        #pragma unroll
        for (int i = 0; i < 8; i++) {
            int id = tid + i * 256;
            int t = id >> 9, rem = id & 511;
            int r = rem >> 3, q = rem & 7;
            uint32_t dst = sb + SOFF(s, t) + r * FP + q * 16;
            const char* src = (const char*)(kvsrc[t] + (size_t)(m0 + r) * CDIM + gcol) + q * 16;
            CP16(dst, src);
        }
    };

    // ---- stage Q (hi/lo 128x64) into stage-1 buffer; kv0 into stage-0 ----
    #pragma unroll
    for (int i = 0; i < 8; i++) {
        int id = tid + i * 256;
        int t = id >> 10, rem = id & 1023;
        int r = rem >> 3, q = rem & 7;
        const char* src = (const char*)((t ? Xl : Xh) + (size_t)(n0 + r) * CDIM + gcol) + q * 16;
        CP16(sb + SOFF(1, 2 * t) + r * FP + q * 16, src);   // 128 rows span tiles 2t,2t+1
    }
    cp_kv(0, 0);
    CP_COMMIT();
    CP_WAIT(0);
    __syncthreads();

    // ---- Q fragments resident for all iterations ----
    uint32_t qa[2][4][4];
    #pragma unroll
    for (int h = 0; h < 2; h++)
        #pragma unroll
        for (int kt = 0; kt < 4; kt++) {
            uint32_t ad = sb + SOFF(1, 2 * h) + (wid * 16 + (lane & 15)) * FP
                        + (kt * 16 + (lane >> 4) * 8) * 2;
            LDSM4(qa[h][kt], ad);
        }
    __syncthreads();   // Q reads done before stage-1 is overwritten by prefetch

    float accO[8][4] = {};
    float mi0 = -CUDART_INF_F, mi1 = -CUDART_INF_F;
    float ls0 = 0.f, ls1 = 0.f;

    const float* lbase = LI + (size_t)(n0 + wid * 16 + g) * NROI + 2 * th;

    for (int it = 0; it < 32; it++) {
        const int s = it & 1;
        if (it < 31) { cp_kv(it + 1, s ^ 1); CP_COMMIT(); CP_WAIT(1); }
        else         { CP_WAIT(0); }
        __syncthreads();

        const uint32_t stK = sb + SOFF(s, 0);
        const uint32_t stV = sb + SOFF(s, 2);

        // ---- S = Q K^T (bf16 split; per-p fragment loads for low reg peak) ----
        float accS[8][4] = {};
        #pragma unroll
        for (int pidx = 0; pidx < 4; pidx++) {
            #pragma unroll
            for (int kt = 0; kt < 4; kt++) {
                uint32_t kh[4], kl[4];
                uint32_t ad = stK + (pidx * 16 + (lane & 15)) * FP
                            + (kt * 16 + (lane >> 4) * 8) * 2;
                LDSM4(kh, ad);
                LDSM4(kl, ad + 64 * FP);
                uint32_t b0h[2] = {kh[0], kh[2]}, b1h[2] = {kh[1], kh[3]};
                uint32_t b0l[2] = {kl[0], kl[2]}, b1l[2] = {kl[1], kl[3]};
                MMA_BF16(accS[2*pidx],   qa[0][kt], b0h);
                MMA_BF16(accS[2*pidx],   qa[0][kt], b0l);
                MMA_BF16(accS[2*pidx],   qa[1][kt], b0h);
                MMA_BF16(accS[2*pidx+1], qa[0][kt], b1h);
                MMA_BF16(accS[2*pidx+1], qa[0][kt], b1l);
                MMA_BF16(accS[2*pidx+1], qa[1][kt], b1h);
            }
        }

        // ---- scores (log2 domain); LI loaded at use ----
        {
            const float* lp = lbase + it * 64;
            #pragma unroll
            for (int nt = 0; nt < 8; nt++) {
                float2 lA = *(const float2*)(lp + nt * 8);
                float2 lB = *(const float2*)(lp + 8 * NROI + nt * 8);
                accS[nt][0] = fmaf(accS[nt][0], SCL8_LOG2E, lA.x);
                accS[nt][1] = fmaf(accS[nt][1], SCL8_LOG2E, lA.y);
                accS[nt][2] = fmaf(accS[nt][2], SCL8_LOG2E, lB.x);
                accS[nt][3] = fmaf(accS[nt][3], SCL8_LOG2E, lB.y);
            }
        }

        // ---- online softmax (base-2) ----
        float mt0 = -CUDART_INF_F, mt1 = -CUDART_INF_F;
        #pragma unroll
        for (int nt = 0; nt < 8; nt++) {
            mt0 = fmaxf(mt0, fmaxf(accS[nt][0], accS[nt][1]));
            mt1 = fmaxf(mt1, fmaxf(accS[nt][2], accS[nt][3]));
        }
        mt0 = fmaxf(mt0, __shfl_xor_sync(0xffffffffu, mt0, 1));
        mt0 = fmaxf(mt0, __shfl_xor_sync(0xffffffffu, mt0, 2));
        mt1 = fmaxf(mt1, __shfl_xor_sync(0xffffffffu, mt1, 1));
        mt1 = fmaxf(mt1, __shfl_xor_sync(0xffffffffu, mt1, 2));
        float mn0 = fmaxf(mi0, mt0), mn1 = fmaxf(mi1, mt1);
        float al0 = ex2f(mi0 - mn0), al1 = ex2f(mi1 - mn1);
        mi0 = mn0; mi1 = mn1;

        uint32_t pa[4][4];
        float rs0 = 0.f, rs1 = 0.f;
        #pragma unroll
        for (int nt = 0; nt < 8; nt++) {
            float p0 = ex2f(accS[nt][0] - mn0 + 10.f);
            float p1 = ex2f(accS[nt][1] - mn0 + 10.f);
            float p2 = ex2f(accS[nt][2] - mn1 + 10.f);
            float p3 = ex2f(accS[nt][3] - mn1 + 10.f);
            rs0 += p0 + p1; rs1 += p2 + p3;
            int kt = nt >> 1, off = (nt & 1) * 2;
            pa[kt][off]     = hf2pk(p1, p0);
            pa[kt][off + 1] = hf2pk(p3, p2);
        }
        rs0 += __shfl_xor_sync(0xffffffffu, rs0, 1);
        rs0 += __shfl_xor_sync(0xffffffffu, rs0, 2);
        rs1 += __shfl_xor_sync(0xffffffffu, rs1, 1);
        rs1 += __shfl_xor_sync(0xffffffffu, rs1, 2);
        ls0 = ls0 * al0 + rs0;
        ls1 = ls1 * al1 + rs1;

        #pragma unroll
        for (int nt = 0; nt < 8; nt++) {
            accO[nt][0] *= al0; accO[nt][1] *= al0;
            accO[nt][2] *= al1; accO[nt][3] *= al1;
        }

        // ---- O += P V (fp16; per-db fragment loads) ----
        #pragma unroll
        for (int kt = 0; kt < 4; kt++) {
            #pragma unroll
            for (int db = 0; db < 4; db++) {
                uint32_t vh[4], vl[4];
                uint32_t ad = stV + (kt * 16 + (lane & 15)) * FP
                            + (db * 16 + (lane >> 4) * 8) * 2;
                LDSM4T(vh, ad);
                LDSM4T(vl, ad + 64 * FP);
                uint32_t bh0[2] = {vh[0], vh[1]}, bh1[2] = {vh[2], vh[3]};
                uint32_t bl0[2] = {vl[0], vl[1]}, bl1[2] = {vl[2], vl[3]};
                MMA_F16(accO[2*db],   pa[kt], bh0);
                MMA_F16(accO[2*db],   pa[kt], bl0);
                MMA_F16(accO[2*db+1], pa[kt], bh1);
                MMA_F16(accO[2*db+1], pa[kt], bl1);
            }
        }
        __syncthreads();
    }

    // ---- epilogue ----
    const float inv0 = 1.f / ls0, inv1 = 1.f / ls1;
    #pragma unroll
    for (int nt = 0; nt < 8; nt++) {
        const int col = grp * DH + nt * 8 + 2 * th;
        float2 bo = *(const float2*)(bout + col);
        const int row = n0 + wid * 16 + g;
        *(float2*)(out + (size_t)row * CDIM + col) =
            make_float2(accO[nt][0] * inv0 + bo.x, accO[nt][1] * inv0 + bo.y);
        *(float2*)(out + (size_t)(row + 8) * CDIM + col) =
            make_float2(accO[nt][2] * inv1 + bo.x, accO[nt][3] * inv1 + bo.y);
    }
}

// ============================================================================
// launch
// ============================================================================
extern "C" void kernel_launch(void* const* d_in, const int* in_sizes, int n_in,
                              void* d_out, int out_size) {
    const float* in_x = (const float*)d_in[0];
    const float* rois = (const float*)d_in[1];
    const float* W0   = (const float*)d_in[2];
    const float* b0   = (const float*)d_in[3];
    const float* W1   = (const float*)d_in[4];
    const float* b1   = (const float*)d_in[5];
    const float* Wout = (const float*)d_in[6];
    const float* bout = (const float*)d_in[7];
    float* out = (float*)d_out;

    void *pA0h,*pA0l,*pA1h,*pA1l,*pA2h,*pA2l,*pW0h,*pW0l,*pW1h,*pW1l,*pWph,*pWpl;
    void *pXh,*pXl,*pVh,*pVl,*pLI;
    cudaGetSymbolAddress(&pA0h, g_A0h); cudaGetSymbolAddress(&pA0l, g_A0l);
    cudaGetSymbolAddress(&pA1h, g_A1h); cudaGetSymbolAddress(&pA1l, g_A1l);
    cudaGetSymbolAddress(&pA2h, g_A2h); cudaGetSymbolAddress(&pA2l, g_A2l);
    cudaGetSymbolAddress(&pW0h, g_W0h); cudaGetSymbolAddress(&pW0l, g_W0l);
    cudaGetSymbolAddress(&pW1h, g_W1h); cudaGetSymbolAddress(&pW1l, g_W1l);
    cudaGetSymbolAddress(&pWph, g_Wph); cudaGetSymbolAddress(&pWpl, g_Wpl);
    cudaGetSymbolAddress(&pXh, g_Xh);   cudaGetSymbolAddress(&pXl, g_Xl);
    cudaGetSymbolAddress(&pVh, g_Vh);   cudaGetSymbolAddress(&pVl, g_Vl);
    cudaGetSymbolAddress(&pLI, g_LI);

    split_all<<<7168, 256>>>(in_x, W0, W1, Wout,
                             (__nv_bfloat16*)pA0h, (__nv_bfloat16*)pA0l,
                             (__nv_bfloat16*)pA2h, (__nv_bfloat16*)pA2l,
                             (__nv_bfloat16*)pW0h, (__nv_bfloat16*)pW0l,
                             (__nv_bfloat16*)pW1h, (__nv_bfloat16*)pW1l,
                             (__nv_bfloat16*)pWph, (__nv_bfloat16*)pWpl);

    logiou_kernel<<<(NROI * NROI) / 256, 256>>>(rois, (float*)pLI);

    cudaFuncSetAttribute(gemm_tc, cudaFuncAttributeMaxDynamicSharedMemorySize, GEMM_SMEM);

    // GEMM0 (mode0) + GEMM2 (mode2) fused in one dual launch (independent)
    GP g0 = {(__nv_bfloat16*)pA0h, (__nv_bfloat16*)pA0l,
             (__nv_bfloat16*)pW0h, (__nv_bfloat16*)pW0l,
             b0, (__nv_bfloat16*)pA1h, (__nv_bfloat16*)pA1l, 0};
    GP g2 = {(__nv_bfloat16*)pA2h, (__nv_bfloat16*)pA2l,
             (__nv_bfloat16*)pWph, (__nv_bfloat16*)pWpl,
             nullptr, (__nv_bfloat16*)pVh, (__nv_bfloat16*)pVl, 2};
    gemm_tc<<<dim3(CDIM / 64, NROI / 128, 2), 256, GEMM_SMEM>>>(g0, g2);

    // GEMM1 (mode1): depends on A1
    GP g1 = {(__nv_bfloat16*)pA1h, (__nv_bfloat16*)pA1l,
             (__nv_bfloat16*)pW1h, (__nv_bfloat16*)pW1l,
             b1, (__nv_bfloat16*)pXh, (__nv_bfloat16*)pXl, 1};
    gemm_tc<<<dim3(CDIM / 64, NROI / 128, 1), 256, GEMM_SMEM>>>(g1, g1);

    // HMMA flash attention (occ 2)
    cudaFuncSetAttribute(flash_hmma, cudaFuncAttributeMaxDynamicSharedMemorySize, FLASH_SMEM);
    flash_hmma<<<dim3(NROI / 128, GRP), 256, FLASH_SMEM>>>(
        (__nv_bfloat16*)pXh, (__nv_bfloat16*)pXl,
        (__nv_bfloat16*)pVh, (__nv_bfloat16*)pVl,
        (float*)pLI, bout, out);
}

// round 12
// speedup vs baseline: 1.5562x; 1.5562x over previous
#include <cuda_runtime.h>
#include <cuda_bf16.h>
#include <cuda_fp16.h>
#include <math_constants.h>
#include <cstdint>

#define NROI 2048
#define CDIM 1024
#define GRP  16
#define DH   64

// ============================================================================
// device scratch
// ============================================================================
__device__ __nv_bfloat16 g_A0h[NROI * CDIM], g_A0l[NROI * CDIM];   // split relu(in_x)
__device__ __nv_bfloat16 g_A1h[NROI * CDIM], g_A1l[NROI * CDIM];   // split relu(H0)
__device__ __nv_bfloat16 g_A2h[NROI * CDIM], g_A2l[NROI * CDIM];   // split in_x
__device__ __nv_bfloat16 g_W0h[CDIM * CDIM], g_W0l[CDIM * CDIM];
__device__ __nv_bfloat16 g_W1h[CDIM * CDIM], g_W1l[CDIM * CDIM];
__device__ __nv_bfloat16 g_Wph[CDIM * CDIM], g_Wpl[CDIM * CDIM];
__device__ __nv_bfloat16 g_Xh[NROI * CDIM], g_Xl[NROI * CDIM];     // embedded X (Q/K), bf16 split
__device__ __half        g_Vh[NROI * CDIM], g_Vl[NROI * CDIM];     // V, fp16 split
__device__ float g_Pt0[NROI * CDIM], g_Pt1[NROI * CDIM];           // split-K partials (GEMM1)
__device__ float g_LI[NROI * NROI];                                 // log2(iou + 1e-6)

// ============================================================================
// PTX helpers
// ============================================================================
__device__ __forceinline__ uint32_t smem_u32(const void* p) {
    uint32_t a;
    asm("{ .reg .u64 t; cvta.to.shared.u64 t, %1; cvt.u32.u64 %0, t; }" : "=r"(a) : "l"(p));
    return a;
}
#define LDSM4(r, addr) \
    asm volatile("ldmatrix.sync.aligned.m8n8.x4.shared.b16 {%0,%1,%2,%3}, [%4];" \
        : "=r"((r)[0]), "=r"((r)[1]), "=r"((r)[2]), "=r"((r)[3]) : "r"(addr))
#define LDSM4T(r, addr) \
    asm volatile("ldmatrix.sync.aligned.m8n8.x4.trans.shared.b16 {%0,%1,%2,%3}, [%4];" \
        : "=r"((r)[0]), "=r"((r)[1]), "=r"((r)[2]), "=r"((r)[3]) : "r"(addr))
#define LDSM2(r, addr) \
    asm volatile("ldmatrix.sync.aligned.m8n8.x2.shared.b16 {%0,%1}, [%2];" \
        : "=r"((r)[0]), "=r"((r)[1]) : "r"(addr))
#define MMA_BF16(c, a, b) \
    asm volatile("mma.sync.aligned.m16n8k16.row.col.f32.bf16.bf16.f32 " \
        "{%0,%1,%2,%3}, {%4,%5,%6,%7}, {%8,%9}, {%0,%1,%2,%3};" \
        : "+f"((c)[0]), "+f"((c)[1]), "+f"((c)[2]), "+f"((c)[3]) \
        : "r"((a)[0]), "r"((a)[1]), "r"((a)[2]), "r"((a)[3]), "r"((b)[0]), "r"((b)[1]))
#define MMA_F16(c, a, b) \
    asm volatile("mma.sync.aligned.m16n8k16.row.col.f32.f16.f16.f32 " \
        "{%0,%1,%2,%3}, {%4,%5,%6,%7}, {%8,%9}, {%0,%1,%2,%3};" \
        : "+f"((c)[0]), "+f"((c)[1]), "+f"((c)[2]), "+f"((c)[3]) \
        : "r"((a)[0]), "r"((a)[1]), "r"((a)[2]), "r"((a)[3]), "r"((b)[0]), "r"((b)[1]))
#define CP16(dst, src)  asm volatile("cp.async.cg.shared.global [%0], [%1], 16;" :: "r"(dst), "l"(src))
#define CP_COMMIT()     asm volatile("cp.async.commit_group;" ::: "memory")
#define CP_WAIT(n)      asm volatile("cp.async.wait_group %0;" :: "n"(n) : "memory")

__device__ __forceinline__ uint32_t bf2pk(float hi, float lo) {
    uint32_t r; asm("cvt.rn.bf16x2.f32 %0, %1, %2;" : "=r"(r) : "f"(hi), "f"(lo)); return r;
}
__device__ __forceinline__ uint32_t hf2pk(float hi, float lo) {
    uint32_t r; asm("cvt.rn.f16x2.f32 %0, %1, %2;" : "=r"(r) : "f"(hi), "f"(lo)); return r;
}
__device__ __forceinline__ float ex2f(float x) {
    float r; asm("ex2.approx.f32 %0, %1;" : "=f"(r) : "f"(x)); return r;
}

// ============================================================================
// merged split kernel (one launch, 5 segments)
// ============================================================================
__global__ __launch_bounds__(256)
void split_all(const float* __restrict__ in_x, const float* __restrict__ W0,
               const float* __restrict__ W1, const float* __restrict__ Wp,
               __nv_bfloat16* __restrict__ a0h, __nv_bfloat16* __restrict__ a0l,
               __nv_bfloat16* __restrict__ a2h, __nv_bfloat16* __restrict__ a2l,
               __nv_bfloat16* __restrict__ w0h, __nv_bfloat16* __restrict__ w0l,
               __nv_bfloat16* __restrict__ w1h, __nv_bfloat16* __restrict__ w1l,
               __nv_bfloat16* __restrict__ wph, __nv_bfloat16* __restrict__ wpl) {
    const int b = blockIdx.x;
    const float* src; __nv_bfloat16 *hi, *lo; int relu = 0, base;
    if      (b < 2048) { src = in_x; hi = a0h; lo = a0l; relu = 1; base = 0; }
    else if (b < 4096) { src = in_x; hi = a2h; lo = a2l; base = 2048; }
    else if (b < 5120) { src = W0;   hi = w0h; lo = w0l; base = 4096; }
    else if (b < 6144) { src = W1;   hi = w1h; lo = w1l; base = 5120; }
    else               { src = Wp;   hi = wph; lo = wpl; base = 6144; }
    int i = (b - base) * 256 + threadIdx.x;
    float4 v = ((const float4*)src)[i];
    if (relu) {
        v.x = fmaxf(v.x, 0.f); v.y = fmaxf(v.y, 0.f);
        v.z = fmaxf(v.z, 0.f); v.w = fmaxf(v.w, 0.f);
    }
    float f[4] = {v.x, v.y, v.z, v.w};
    uint32_t hu[2], lu[2];
    #pragma unroll
    for (int j = 0; j < 2; j++) {
        uint32_t h = bf2pk(f[2*j+1], f[2*j]);
        float e0 = __uint_as_float(h << 16);
        float e1 = __uint_as_float(h & 0xffff0000u);
        hu[j] = h;
        lu[j] = bf2pk(f[2*j+1] - e1, f[2*j] - e0);
    }
    ((uint2*)hi)[i] = make_uint2(hu[0], hu[1]);
    ((uint2*)lo)[i] = make_uint2(lu[0], lu[1]);
}

// ============================================================================
// HMMA split-bf16 GEMM, 128x128 tile (R10-proven), dual-problem via gridDim.z
//   mode 0: relu(acc+bias)->bf16 split      mode 2: acc->fp16 split
//   mode 3: acc->fp32 partial (split-K)
// ============================================================================
struct GP {
    const __nv_bfloat16 *Ah, *Al, *Bh, *Bl;
    const float* bias;
    __nv_bfloat16 *oHi, *oLo;
    float* oF;
    int kStart, nChunks, mode;
};

#define TILE_BYTES  10240            // 128 rows x 80 B
#define STAGE_BYTES (4 * TILE_BYTES)
#define GEMM_SMEM   (2 * STAGE_BYTES)  // 81920

__global__ __launch_bounds__(256, 2)
void gemm_tc(GP p0, GP p1) {
    const GP p = (blockIdx.z == 0) ? p0 : p1;
    extern __shared__ char smc[];
    const uint32_t sb = smem_u32(smc);
    const int tid = threadIdx.x;
    const int wid = tid >> 5, lane = tid & 31;
    const int wm = wid & 1, wn = wid >> 1;
    const int row0 = blockIdx.y * 128;
    const int col0 = blockIdx.x * 128;

    const __nv_bfloat16* srcs[4] = {p.Ah, p.Al, p.Bh, p.Bl};

    auto cp_chunk = [&](int c, int s) {
        const int kb = (p.kStart + c) * 32;
        #pragma unroll
        for (int t = 0; t < 4; t++) {
            const char* src = (const char*)(srcs[t] + (size_t)((t < 2) ? row0 : col0) * CDIM + kb);
            uint32_t dst = sb + s * STAGE_BYTES + t * TILE_BYTES;
            #pragma unroll
            for (int i = 0; i < 2; i++) {
                int id = tid + i * 256;
                int r = id >> 2, q = id & 3;
                CP16(dst + r * 80 + q * 16, src + (size_t)r * (CDIM * 2) + q * 16);
            }
        }
    };

    float acc[4][4][4] = {};
    cp_chunk(0, 0); CP_COMMIT();

    const int NC = p.nChunks;
    for (int c = 0; c < NC; c++) {
        const int s = c & 1;
        if (c < NC - 1) { cp_chunk(c + 1, s ^ 1); CP_COMMIT(); CP_WAIT(1); }
        else            { CP_WAIT(0); }
        __syncthreads();

        const uint32_t stg = sb + s * STAGE_BYTES;
        #pragma unroll
        for (int ks = 0; ks < 2; ks++) {
            uint32_t ah[4][4], al[4][4], bh[4][2], bl[4][2];
            {
                const int kk = ks * 16 + (lane >> 4) * 8;
                #pragma unroll
                for (int mt = 0; mt < 4; mt++) {
                    const int ra = wm * 64 + mt * 16 + (lane & 15);
                    uint32_t ad = stg + ra * 80 + kk * 2;
                    LDSM4(ah[mt], ad);
                    LDSM4(al[mt], ad + TILE_BYTES);
                }
            }
            {
                const int kk = ks * 16 + ((lane >> 3) & 1) * 8;
                #pragma unroll
                for (int nt = 0; nt < 4; nt++) {
                    const int rb = wn * 32 + nt * 8 + (lane & 7);
                    uint32_t bd = stg + 2 * TILE_BYTES + rb * 80 + kk * 2;
                    LDSM2(bh[nt], bd);
                    LDSM2(bl[nt], bd + TILE_BYTES);
                }
            }
            #pragma unroll
            for (int mt = 0; mt < 4; mt++)
                #pragma unroll
                for (int nt = 0; nt < 4; nt++) {
                    MMA_BF16(acc[mt][nt], ah[mt], bh[nt]);
                    MMA_BF16(acc[mt][nt], ah[mt], bl[nt]);
                    MMA_BF16(acc[mt][nt], al[mt], bh[nt]);
                }
        }
        __syncthreads();
    }

    const int g = lane >> 2, th = lane & 3;
    #pragma unroll
    for (int mt = 0; mt < 4; mt++)
        #pragma unroll
        for (int nt = 0; nt < 4; nt++) {
            const int row = row0 + wm * 64 + mt * 16 + g;
            const int col = col0 + wn * 32 + nt * 8 + th * 2;
            float2 bv = make_float2(0.f, 0.f);
            if (p.mode == 0) bv = *(const float2*)(p.bias + col);
            const float* cc = acc[mt][nt];
            #pragma unroll
            for (int h = 0; h < 2; h++) {
                float v0 = cc[h * 2 + 0] + bv.x;
                float v1 = cc[h * 2 + 1] + bv.y;
                size_t o = (size_t)(row + h * 8) * CDIM + col;
                if (p.mode == 3) {
                    *(float2*)(p.oF + o) = make_float2(v0, v1);
                } else if (p.mode == 2) {
                    uint32_t hp = hf2pk(v1, v0);
                    __half2 hh = *(__half2*)&hp;
                    float2 e = __half22float2(hh);
                    *(uint32_t*)(p.oHi + o) = hp;
                    *(uint32_t*)(p.oLo + o) = hf2pk(v1 - e.y, v0 - e.x);
                } else {   // mode 0
                    v0 = fmaxf(v0, 0.f); v1 = fmaxf(v1, 0.f);
                    uint32_t hp = bf2pk(v1, v0);
                    float e0 = __uint_as_float(hp << 16);
                    float e1 = __uint_as_float(hp & 0xffff0000u);
                    *(uint32_t*)(p.oHi + o) = hp;
                    *(uint32_t*)(p.oLo + o) = bf2pk(v1 - e1, v0 - e0);
                }
            }
        }
}

// ============================================================================
// split-K combine: X = bf16split(P0 + P1 + bias)
// ============================================================================
__global__ __launch_bounds__(256)
void combine_kernel(const float* __restrict__ P0, const float* __restrict__ P1,
                    const float* __restrict__ bias,
                    __nv_bfloat16* __restrict__ hi, __nv_bfloat16* __restrict__ lo) {
    int i = blockIdx.x * blockDim.x + threadIdx.x;      // float4 index
    float4 a = ((const float4*)P0)[i];
    float4 b = ((const float4*)P1)[i];
    int col = (i & (CDIM / 4 - 1)) * 4;
    float4 bv = *(const float4*)(bias + col);
    float f[4] = {a.x + b.x + bv.x, a.y + b.y + bv.y,
                  a.z + b.z + bv.z, a.w + b.w + bv.w};
    uint32_t hu[2], lu[2];
    #pragma unroll
    for (int j = 0; j < 2; j++) {
        uint32_t h = bf2pk(f[2*j+1], f[2*j]);
        float e0 = __uint_as_float(h << 16);
        float e1 = __uint_as_float(h & 0xffff0000u);
        hu[j] = h;
        lu[j] = bf2pk(f[2*j+1] - e1, f[2*j] - e0);
    }
    ((uint2*)hi)[i] = make_uint2(hu[0], hu[1]);
    ((uint2*)lo)[i] = make_uint2(lu[0], lu[1]);
}

// ============================================================================
// log2(IoU + 1e-6) table
// ============================================================================
__global__ __launch_bounds__(256)
void logiou_kernel(const float* __restrict__ rois, float* __restrict__ li) {
    int idx = blockIdx.x * blockDim.x + threadIdx.x;
    int n = idx >> 11;
    int m = idx & 2047;
    const float* a = rois + n * 5 + 1;
    const float* b = rois + m * 5 + 1;
    float ax1 = a[0], ay1 = a[1], ax2 = a[2], ay2 = a[3];
    float bx1 = b[0], by1 = b[1], bx2 = b[2], by2 = b[3];
    float areaA = (ax2 - ax1 + 1.f) * (ay2 - ay1 + 1.f);
    float areaB = (bx2 - bx1 + 1.f) * (by2 - by1 + 1.f);
    float w = fminf(ax2, bx2) - fmaxf(ax1, bx1) + 1.f; w = fmaxf(w, 0.f);
    float h = fminf(ay2, by2) - fmaxf(ay1, by1) + 1.f; h = fmaxf(h, 0.f);
    float inter = w * h;
    float iou = __fdividef(inter, areaA + areaB - inter);
    li[idx] = __log2f(iou + 1e-6f);
}

// ============================================================================
// HMMA flash attention — R10 version verbatim (no reg cap, 1 CTA/SM)
// ============================================================================
#define FP 144
#define QOFF(h)     ((h) * (128 * FP))
#define SOFF(s, t)  (2 * 128 * FP + (s) * (4 * 64 * FP) + (t) * (64 * FP))
#define FLASH_SMEM  (2 * 128 * FP + 2 * 4 * 64 * FP)   // 110592 B
#define SCL8_LOG2E  0.1803368801111204f                 // 0.125 * log2(e)

__global__ __launch_bounds__(256)
void flash_hmma(const __nv_bfloat16* __restrict__ Xh, const __nv_bfloat16* __restrict__ Xl,
                const __nv_bfloat16* __restrict__ Vh, const __nv_bfloat16* __restrict__ Vl,
                const float* __restrict__ LI, const float* __restrict__ bout,
                float* __restrict__ out) {
    extern __shared__ char smc[];
    const uint32_t sb = smem_u32(smc);
    const int tid = threadIdx.x;
    const int wid = tid >> 5, lane = tid & 31;
    const int g = lane >> 2, th = lane & 3;
    const int n0 = blockIdx.x * 128;
    const int grp = blockIdx.y;
    const size_t gcol = (size_t)grp * DH;

    const __nv_bfloat16* kvsrc[4] = {Xh, Xl, Vh, Vl};

    #pragma unroll
    for (int i = 0; i < 8; i++) {
        int id = tid + i * 256;
        int t = id >> 10, rem = id & 1023;
        int r = rem >> 3, q = rem & 7;
        const char* src = (const char*)((t ? Xl : Xh) + (size_t)(n0 + r) * CDIM + gcol) + q * 16;
        CP16(sb + QOFF(t) + r * FP + q * 16, src);
    }
    auto cp_kv = [&](int it, int s) {
        const int m0 = it * 64;
        #pragma unroll
        for (int i = 0; i < 8; i++) {
            int id = tid + i * 256;
            int t = id >> 9, rem = id & 511;
            int r = rem >> 3, q = rem & 7;
            uint32_t dst = sb + SOFF(s, t) + r * FP + q * 16;
            const char* src = (const char*)(kvsrc[t] + (size_t)(m0 + r) * CDIM + gcol) + q * 16;
            CP16(dst, src);
        }
    };

    cp_kv(0, 0);
    CP_COMMIT();
    CP_WAIT(0);
    __syncthreads();

    uint32_t qa[2][4][4];
    #pragma unroll
    for (int h = 0; h < 2; h++)
        #pragma unroll
        for (int kt = 0; kt < 4; kt++) {
            uint32_t ad = sb + QOFF(h) + (wid * 16 + (lane & 15)) * FP
                        + (kt * 16 + (lane >> 4) * 8) * 2;
            LDSM4(qa[h][kt], ad);
        }

    float accO[8][4] = {};
    float mi0 = -CUDART_INF_F, mi1 = -CUDART_INF_F;
    float ls0 = 0.f, ls1 = 0.f;

    const float* lbase = LI + (size_t)(n0 + wid * 16 + g) * NROI + 2 * th;

    for (int it = 0; it < 32; it++) {
        const int s = it & 1;

        float2 liA[8], liB[8];
        {
            const float* lp = lbase + it * 64;
            #pragma unroll
            for (int nt = 0; nt < 8; nt++) {
                liA[nt] = *(const float2*)(lp + nt * 8);
                liB[nt] = *(const float2*)(lp + 8 * NROI + nt * 8);
            }
        }

        if (it < 31) { cp_kv(it + 1, s ^ 1); CP_COMMIT(); CP_WAIT(1); }
        else         { CP_WAIT(0); }
        __syncthreads();

        const uint32_t stK = sb + SOFF(s, 0);
        const uint32_t stV = sb + SOFF(s, 2);

        float accS[8][4] = {};
        #pragma unroll
        for (int kt = 0; kt < 4; kt++) {
            uint32_t kh[4][4], kl[4][4];
            #pragma unroll
            for (int p = 0; p < 4; p++) {
                uint32_t ad = stK + (p * 16 + (lane & 15)) * FP
                            + (kt * 16 + (lane >> 4) * 8) * 2;
                LDSM4(kh[p], ad);
                LDSM4(kl[p], ad + 64 * FP);
            }
            #pragma unroll
            for (int p = 0; p < 4; p++) {
                uint32_t b0h[2] = {kh[p][0], kh[p][2]}, b1h[2] = {kh[p][1], kh[p][3]};
                uint32_t b0l[2] = {kl[p][0], kl[p][2]}, b1l[2] = {kl[p][1], kl[p][3]};
                MMA_BF16(accS[2*p],   qa[0][kt], b0h);
                MMA_BF16(accS[2*p],   qa[0][kt], b0l);
                MMA_BF16(accS[2*p],   qa[1][kt], b0h);
                MMA_BF16(accS[2*p+1], qa[0][kt], b1h);
                MMA_BF16(accS[2*p+1], qa[0][kt], b1l);
                MMA_BF16(accS[2*p+1], qa[1][kt], b1h);
            }
        }

        #pragma unroll
        for (int nt = 0; nt < 8; nt++) {
            accS[nt][0] = fmaf(accS[nt][0], SCL8_LOG2E, liA[nt].x);
            accS[nt][1] = fmaf(accS[nt][1], SCL8_LOG2E, liA[nt].y);
            accS[nt][2] = fmaf(accS[nt][2], SCL8_LOG2E, liB[nt].x);
            accS[nt][3] = fmaf(accS[nt][3], SCL8_LOG2E, liB[nt].y);
        }

        float mt0 = -CUDART_INF_F, mt1 = -CUDART_INF_F;
        #pragma unroll
        for (int nt = 0; nt < 8; nt++) {
            mt0 = fmaxf(mt0, fmaxf(accS[nt][0], accS[nt][1]));
            mt1 = fmaxf(mt1, fmaxf(accS[nt][2], accS[nt][3]));
        }
        mt0 = fmaxf(mt0, __shfl_xor_sync(0xffffffffu, mt0, 1));
        mt0 = fmaxf(mt0, __shfl_xor_sync(0xffffffffu, mt0, 2));
        mt1 = fmaxf(mt1, __shfl_xor_sync(0xffffffffu, mt1, 1));
        mt1 = fmaxf(mt1, __shfl_xor_sync(0xffffffffu, mt1, 2));
        float mn0 = fmaxf(mi0, mt0), mn1 = fmaxf(mi1, mt1);
        float al0 = ex2f(mi0 - mn0), al1 = ex2f(mi1 - mn1);
        mi0 = mn0; mi1 = mn1;

        uint32_t pa[4][4];
        float rs0 = 0.f, rs1 = 0.f;
        #pragma unroll
        for (int nt = 0; nt < 8; nt++) {
            float p0 = ex2f(accS[nt][0] - mn0 + 10.f);
            float p1 = ex2f(accS[nt][1] - mn0 + 10.f);
            float p2 = ex2f(accS[nt][2] - mn1 + 10.f);
            float p3 = ex2f(accS[nt][3] - mn1 + 10.f);
            rs0 += p0 + p1; rs1 += p2 + p3;
            int kt = nt >> 1, off = (nt & 1) * 2;
            pa[kt][off]     = hf2pk(p1, p0);
            pa[kt][off + 1] = hf2pk(p3, p2);
        }
        rs0 += __shfl_xor_sync(0xffffffffu, rs0, 1);
        rs0 += __shfl_xor_sync(0xffffffffu, rs0, 2);
        rs1 += __shfl_xor_sync(0xffffffffu, rs1, 1);
        rs1 += __shfl_xor_sync(0xffffffffu, rs1, 2);
        ls0 = ls0 * al0 + rs0;
        ls1 = ls1 * al1 + rs1;

        #pragma unroll
        for (int nt = 0; nt < 8; nt++) {
            accO[nt][0] *= al0; accO[nt][1] *= al0;
            accO[nt][2] *= al1; accO[nt][3] *= al1;
        }

        #pragma unroll
        for (int kt = 0; kt < 4; kt++) {
            uint32_t vh[4][4], vl[4][4];
            #pragma unroll
            for (int db = 0; db < 4; db++) {
                uint32_t ad = stV + (kt * 16 + (lane & 15)) * FP
                            + (db * 16 + (lane >> 4) * 8) * 2;
                LDSM4T(vh[db], ad);
                LDSM4T(vl[db], ad + 64 * FP);
            }
            #pragma unroll
            for (int db = 0; db < 4; db++) {
                uint32_t bh0[2] = {vh[db][0], vh[db][1]}, bh1[2] = {vh[db][2], vh[db][3]};
                uint32_t bl0[2] = {vl[db][0], vl[db][1]}, bl1[2] = {vl[db][2], vl[db][3]};
                MMA_F16(accO[2*db],   pa[kt], bh0);
                MMA_F16(accO[2*db],   pa[kt], bl0);
                MMA_F16(accO[2*db+1], pa[kt], bh1);
                MMA_F16(accO[2*db+1], pa[kt], bl1);
            }
        }
        __syncthreads();
    }

    const float inv0 = 1.f / ls0, inv1 = 1.f / ls1;
    #pragma unroll
    for (int nt = 0; nt < 8; nt++) {
        const int col = grp * DH + nt * 8 + 2 * th;
        float2 bo = *(const float2*)(bout + col);
        const int row = n0 + wid * 16 + g;
        *(float2*)(out + (size_t)row * CDIM + col) =
            make_float2(accO[nt][0] * inv0 + bo.x, accO[nt][1] * inv0 + bo.y);
        *(float2*)(out + (size_t)(row + 8) * CDIM + col) =
            make_float2(accO[nt][2] * inv1 + bo.x, accO[nt][3] * inv1 + bo.y);
    }
}

// ============================================================================
// launch
// ============================================================================
extern "C" void kernel_launch(void* const* d_in, const int* in_sizes, int n_in,
                              void* d_out, int out_size) {
    const float* in_x = (const float*)d_in[0];
    const float* rois = (const float*)d_in[1];
    const float* W0   = (const float*)d_in[2];
    const float* b0   = (const float*)d_in[3];
    const float* W1   = (const float*)d_in[4];
    const float* b1   = (const float*)d_in[5];
    const float* Wout = (const float*)d_in[6];
    const float* bout = (const float*)d_in[7];
    float* out = (float*)d_out;

    void *pA0h,*pA0l,*pA1h,*pA1l,*pA2h,*pA2l,*pW0h,*pW0l,*pW1h,*pW1l,*pWph,*pWpl;
    void *pXh,*pXl,*pVh,*pVl,*pLI,*pPt0,*pPt1;
    cudaGetSymbolAddress(&pA0h, g_A0h); cudaGetSymbolAddress(&pA0l, g_A0l);
    cudaGetSymbolAddress(&pA1h, g_A1h); cudaGetSymbolAddress(&pA1l, g_A1l);
    cudaGetSymbolAddress(&pA2h, g_A2h); cudaGetSymbolAddress(&pA2l, g_A2l);
    cudaGetSymbolAddress(&pW0h, g_W0h); cudaGetSymbolAddress(&pW0l, g_W0l);
    cudaGetSymbolAddress(&pW1h, g_W1h); cudaGetSymbolAddress(&pW1l, g_W1l);
    cudaGetSymbolAddress(&pWph, g_Wph); cudaGetSymbolAddress(&pWpl, g_Wpl);
    cudaGetSymbolAddress(&pXh, g_Xh);   cudaGetSymbolAddress(&pXl, g_Xl);
    cudaGetSymbolAddress(&pVh, g_Vh);   cudaGetSymbolAddress(&pVl, g_Vl);
    cudaGetSymbolAddress(&pPt0, g_Pt0); cudaGetSymbolAddress(&pPt1, g_Pt1);
    cudaGetSymbolAddress(&pLI, g_LI);

    split_all<<<7168, 256>>>(in_x, W0, W1, Wout,
                             (__nv_bfloat16*)pA0h, (__nv_bfloat16*)pA0l,
                             (__nv_bfloat16*)pA2h, (__nv_bfloat16*)pA2l,
                             (__nv_bfloat16*)pW0h, (__nv_bfloat16*)pW0l,
                             (__nv_bfloat16*)pW1h, (__nv_bfloat16*)pW1l,
                             (__nv_bfloat16*)pWph, (__nv_bfloat16*)pWpl);

    logiou_kernel<<<(NROI * NROI) / 256, 256>>>(rois, (float*)pLI);

    cudaFuncSetAttribute(gemm_tc, cudaFuncAttributeMaxDynamicSharedMemorySize, GEMM_SMEM);

    // GEMM0 (mode0) ∥ GEMM2 (mode2): 256 CTAs, 2 CTAs/SM -> one wave
    GP g0 = {(__nv_bfloat16*)pA0h, (__nv_bfloat16*)pA0l,
             (__nv_bfloat16*)pW0h, (__nv_bfloat16*)pW0l,
             b0, (__nv_bfloat16*)pA1h, (__nv_bfloat16*)pA1l, nullptr, 0, 32, 0};
    GP g2 = {(__nv_bfloat16*)pA2h, (__nv_bfloat16*)pA2l,
             (__nv_bfloat16*)pWph, (__nv_bfloat16*)pWpl,
             nullptr, (__nv_bfloat16*)pVh, (__nv_bfloat16*)pVl, nullptr, 0, 32, 2};
    gemm_tc<<<dim3(CDIM / 128, NROI / 128, 2), 256, GEMM_SMEM>>>(g0, g2);

    // GEMM1 split-K=2 (mode3 partials): 256 CTAs, one wave
    GP g1a = {(__nv_bfloat16*)pA1h, (__nv_bfloat16*)pA1l,
              (__nv_bfloat16*)pW1h, (__nv_bfloat16*)pW1l,
              nullptr, nullptr, nullptr, (float*)pPt0, 0, 16, 3};
    GP g1b = {(__nv_bfloat16*)pA1h, (__nv_bfloat16*)pA1l,
              (__nv_bfloat16*)pW1h, (__nv_bfloat16*)pW1l,
              nullptr, nullptr, nullptr, (float*)pPt1, 16, 16, 3};
    gemm_tc<<<dim3(CDIM / 128, NROI / 128, 2), 256, GEMM_SMEM>>>(g1a, g1b);

    // combine partials -> X (bf16 split)
    combine_kernel<<<(NROI * CDIM / 4) / 256, 256>>>((float*)pPt0, (float*)pPt1, b1,
                                                     (__nv_bfloat16*)pXh, (__nv_bfloat16*)pXl);

    // HMMA flash attention (R10)
    cudaFuncSetAttribute(flash_hmma, cudaFuncAttributeMaxDynamicSharedMemorySize, FLASH_SMEM);
    flash_hmma<<<dim3(NROI / 128, GRP), 256, FLASH_SMEM>>>(
        (__nv_bfloat16*)pXh, (__nv_bfloat16*)pXl,
        (__nv_bfloat16*)pVh, (__nv_bfloat16*)pVl,
        (float*)pLI, bout, out);
}

// round 13
// speedup vs baseline: 1.6855x; 1.0831x over previous
#include <cuda_runtime.h>
#include <cuda_bf16.h>
#include <cuda_fp16.h>
#include <math_constants.h>
#include <cstdint>

#define NROI 2048
#define CDIM 1024
#define GRP  16
#define DH   64

// ============================================================================
// device scratch
// ============================================================================
__device__ __nv_bfloat16 g_A0h[NROI * CDIM], g_A0l[NROI * CDIM];   // split relu(in_x)
__device__ __nv_bfloat16 g_A1h[NROI * CDIM], g_A1l[NROI * CDIM];   // split relu(H0)
__device__ __nv_bfloat16 g_A2h[NROI * CDIM], g_A2l[NROI * CDIM];   // split in_x
__device__ __nv_bfloat16 g_W0h[CDIM * CDIM], g_W0l[CDIM * CDIM];
__device__ __nv_bfloat16 g_W1h[CDIM * CDIM], g_W1l[CDIM * CDIM];
__device__ __nv_bfloat16 g_Wph[CDIM * CDIM], g_Wpl[CDIM * CDIM];
__device__ __nv_bfloat16 g_Xh[NROI * CDIM], g_Xl[NROI * CDIM];     // embedded X (Q/K), bf16 split
__device__ __half        g_Vh[NROI * CDIM];                         // V, single fp16
__device__ float g_Pt0[NROI * CDIM], g_Pt1[NROI * CDIM];           // split-K partials (GEMM1)
__device__ float g_LI[NROI * NROI];                                 // log2(iou + 1e-6)

// ============================================================================
// PTX helpers
// ============================================================================
__device__ __forceinline__ uint32_t smem_u32(const void* p) {
    uint32_t a;
    asm("{ .reg .u64 t; cvta.to.shared.u64 t, %1; cvt.u32.u64 %0, t; }" : "=r"(a) : "l"(p));
    return a;
}
#define LDSM4(r, addr) \
    asm volatile("ldmatrix.sync.aligned.m8n8.x4.shared.b16 {%0,%1,%2,%3}, [%4];" \
        : "=r"((r)[0]), "=r"((r)[1]), "=r"((r)[2]), "=r"((r)[3]) : "r"(addr))
#define LDSM4T(r, addr) \
    asm volatile("ldmatrix.sync.aligned.m8n8.x4.trans.shared.b16 {%0,%1,%2,%3}, [%4];" \
        : "=r"((r)[0]), "=r"((r)[1]), "=r"((r)[2]), "=r"((r)[3]) : "r"(addr))
#define LDSM2(r, addr) \
    asm volatile("ldmatrix.sync.aligned.m8n8.x2.shared.b16 {%0,%1}, [%2];" \
        : "=r"((r)[0]), "=r"((r)[1]) : "r"(addr))
#define MMA_BF16(c, a, b) \
    asm volatile("mma.sync.aligned.m16n8k16.row.col.f32.bf16.bf16.f32 " \
        "{%0,%1,%2,%3}, {%4,%5,%6,%7}, {%8,%9}, {%0,%1,%2,%3};" \
        : "+f"((c)[0]), "+f"((c)[1]), "+f"((c)[2]), "+f"((c)[3]) \
        : "r"((a)[0]), "r"((a)[1]), "r"((a)[2]), "r"((a)[3]), "r"((b)[0]), "r"((b)[1]))
#define MMA_F16(c, a, b) \
    asm volatile("mma.sync.aligned.m16n8k16.row.col.f32.f16.f16.f32 " \
        "{%0,%1,%2,%3}, {%4,%5,%6,%7}, {%8,%9}, {%0,%1,%2,%3};" \
        : "+f"((c)[0]), "+f"((c)[1]), "+f"((c)[2]), "+f"((c)[3]) \
        : "r"((a)[0]), "r"((a)[1]), "r"((a)[2]), "r"((a)[3]), "r"((b)[0]), "r"((b)[1]))
#define CP16(dst, src)  asm volatile("cp.async.cg.shared.global [%0], [%1], 16;" :: "r"(dst), "l"(src))
#define CP_COMMIT()     asm volatile("cp.async.commit_group;" ::: "memory")
#define CP_WAIT(n)      asm volatile("cp.async.wait_group %0;" :: "n"(n) : "memory")

__device__ __forceinline__ uint32_t bf2pk(float hi, float lo) {
    uint32_t r; asm("cvt.rn.bf16x2.f32 %0, %1, %2;" : "=r"(r) : "f"(hi), "f"(lo)); return r;
}
__device__ __forceinline__ uint32_t hf2pk(float hi, float lo) {
    uint32_t r; asm("cvt.rn.f16x2.f32 %0, %1, %2;" : "=r"(r) : "f"(hi), "f"(lo)); return r;
}
__device__ __forceinline__ float ex2f(float x) {
    float r; asm("ex2.approx.f32 %0, %1;" : "=f"(r) : "f"(x)); return r;
}

// ============================================================================
// merged prep kernel: 5 split segments + log2-IoU table, one launch
//   blocks [0,7168): fp32 -> (hi,lo) bf16 splits
//   blocks [7168, 23552): log2(iou + 1e-6)
// ============================================================================
__global__ __launch_bounds__(256)
void prep_all(const float* __restrict__ in_x, const float* __restrict__ W0,
              const float* __restrict__ W1, const float* __restrict__ Wp,
              const float* __restrict__ rois, float* __restrict__ li,
              __nv_bfloat16* __restrict__ a0h, __nv_bfloat16* __restrict__ a0l,
              __nv_bfloat16* __restrict__ a2h, __nv_bfloat16* __restrict__ a2l,
              __nv_bfloat16* __restrict__ w0h, __nv_bfloat16* __restrict__ w0l,
              __nv_bfloat16* __restrict__ w1h, __nv_bfloat16* __restrict__ w1l,
              __nv_bfloat16* __restrict__ wph, __nv_bfloat16* __restrict__ wpl) {
    const int b = blockIdx.x;
    if (b >= 7168) {                       // ---- log-IoU segment ----
        int idx = (b - 7168) * 256 + threadIdx.x;
        int n = idx >> 11;
        int m = idx & 2047;
        const float* a = rois + n * 5 + 1;
        const float* bb = rois + m * 5 + 1;
        float ax1 = a[0], ay1 = a[1], ax2 = a[2], ay2 = a[3];
        float bx1 = bb[0], by1 = bb[1], bx2 = bb[2], by2 = bb[3];
        float areaA = (ax2 - ax1 + 1.f) * (ay2 - ay1 + 1.f);
        float areaB = (bx2 - bx1 + 1.f) * (by2 - by1 + 1.f);
        float w = fminf(ax2, bx2) - fmaxf(ax1, bx1) + 1.f; w = fmaxf(w, 0.f);
        float h = fminf(ay2, by2) - fmaxf(ay1, by1) + 1.f; h = fmaxf(h, 0.f);
        float inter = w * h;
        float iou = __fdividef(inter, areaA + areaB - inter);
        li[idx] = __log2f(iou + 1e-6f);
        return;
    }
    const float* src; __nv_bfloat16 *hi, *lo; int relu = 0, base;
    if      (b < 2048) { src = in_x; hi = a0h; lo = a0l; relu = 1; base = 0; }
    else if (b < 4096) { src = in_x; hi = a2h; lo = a2l; base = 2048; }
    else if (b < 5120) { src = W0;   hi = w0h; lo = w0l; base = 4096; }
    else if (b < 6144) { src = W1;   hi = w1h; lo = w1l; base = 5120; }
    else               { src = Wp;   hi = wph; lo = wpl; base = 6144; }
    int i = (b - base) * 256 + threadIdx.x;
    float4 v = ((const float4*)src)[i];
    if (relu) {
        v.x = fmaxf(v.x, 0.f); v.y = fmaxf(v.y, 0.f);
        v.z = fmaxf(v.z, 0.f); v.w = fmaxf(v.w, 0.f);
    }
    float f[4] = {v.x, v.y, v.z, v.w};
    uint32_t hu[2], lu[2];
    #pragma unroll
    for (int j = 0; j < 2; j++) {
        uint32_t h = bf2pk(f[2*j+1], f[2*j]);
        float e0 = __uint_as_float(h << 16);
        float e1 = __uint_as_float(h & 0xffff0000u);
        hu[j] = h;
        lu[j] = bf2pk(f[2*j+1] - e1, f[2*j] - e0);
    }
    ((uint2*)hi)[i] = make_uint2(hu[0], hu[1]);
    ((uint2*)lo)[i] = make_uint2(lu[0], lu[1]);
}

// ============================================================================
// HMMA split-bf16 GEMM, 128x128 tile, dual-problem via gridDim.z
//   mode 0: relu(acc+bias)->bf16 split    mode 2: acc->single fp16
//   mode 3: acc->fp32 partial (split-K)
// ============================================================================
struct GP {
    const __nv_bfloat16 *Ah, *Al, *Bh, *Bl;
    const float* bias;
    __nv_bfloat16 *oHi, *oLo;
    float* oF;
    int kStart, nChunks, mode;
};

#define TILE_BYTES  10240            // 128 rows x 80 B
#define STAGE_BYTES (4 * TILE_BYTES)
#define GEMM_SMEM   (2 * STAGE_BYTES)  // 81920

__global__ __launch_bounds__(256, 2)
void gemm_tc(GP p0, GP p1) {
    const GP p = (blockIdx.z == 0) ? p0 : p1;
    extern __shared__ char smc[];
    const uint32_t sb = smem_u32(smc);
    const int tid = threadIdx.x;
    const int wid = tid >> 5, lane = tid & 31;
    const int wm = wid & 1, wn = wid >> 1;
    const int row0 = blockIdx.y * 128;
    const int col0 = blockIdx.x * 128;

    const __nv_bfloat16* srcs[4] = {p.Ah, p.Al, p.Bh, p.Bl};

    auto cp_chunk = [&](int c, int s) {
        const int kb = (p.kStart + c) * 32;
        #pragma unroll
        for (int t = 0; t < 4; t++) {
            const char* src = (const char*)(srcs[t] + (size_t)((t < 2) ? row0 : col0) * CDIM + kb);
            uint32_t dst = sb + s * STAGE_BYTES + t * TILE_BYTES;
            #pragma unroll
            for (int i = 0; i < 2; i++) {
                int id = tid + i * 256;
                int r = id >> 2, q = id & 3;
                CP16(dst + r * 80 + q * 16, src + (size_t)r * (CDIM * 2) + q * 16);
            }
        }
    };

    float acc[4][4][4] = {};
    cp_chunk(0, 0); CP_COMMIT();

    const int NC = p.nChunks;
    for (int c = 0; c < NC; c++) {
        const int s = c & 1;
        if (c < NC - 1) { cp_chunk(c + 1, s ^ 1); CP_COMMIT(); CP_WAIT(1); }
        else            { CP_WAIT(0); }
        __syncthreads();

        const uint32_t stg = sb + s * STAGE_BYTES;
        #pragma unroll
        for (int ks = 0; ks < 2; ks++) {
            uint32_t ah[4][4], al[4][4], bh[4][2], bl[4][2];
            {
                const int kk = ks * 16 + (lane >> 4) * 8;
                #pragma unroll
                for (int mt = 0; mt < 4; mt++) {
                    const int ra = wm * 64 + mt * 16 + (lane & 15);
                    uint32_t ad = stg + ra * 80 + kk * 2;
                    LDSM4(ah[mt], ad);
                    LDSM4(al[mt], ad + TILE_BYTES);
                }
            }
            {
                const int kk = ks * 16 + ((lane >> 3) & 1) * 8;
                #pragma unroll
                for (int nt = 0; nt < 4; nt++) {
                    const int rb = wn * 32 + nt * 8 + (lane & 7);
                    uint32_t bd = stg + 2 * TILE_BYTES + rb * 80 + kk * 2;
                    LDSM2(bh[nt], bd);
                    LDSM2(bl[nt], bd + TILE_BYTES);
                }
            }
            #pragma unroll
            for (int mt = 0; mt < 4; mt++)
                #pragma unroll
                for (int nt = 0; nt < 4; nt++) {
                    MMA_BF16(acc[mt][nt], ah[mt], bh[nt]);
                    MMA_BF16(acc[mt][nt], ah[mt], bl[nt]);
                    MMA_BF16(acc[mt][nt], al[mt], bh[nt]);
                }
        }
        __syncthreads();
    }

    const int g = lane >> 2, th = lane & 3;
    #pragma unroll
    for (int mt = 0; mt < 4; mt++)
        #pragma unroll
        for (int nt = 0; nt < 4; nt++) {
            const int row = row0 + wm * 64 + mt * 16 + g;
            const int col = col0 + wn * 32 + nt * 8 + th * 2;
            float2 bv = make_float2(0.f, 0.f);
            if (p.mode == 0) bv = *(const float2*)(p.bias + col);
            const float* cc = acc[mt][nt];
            #pragma unroll
            for (int h = 0; h < 2; h++) {
                float v0 = cc[h * 2 + 0] + bv.x;
                float v1 = cc[h * 2 + 1] + bv.y;
                size_t o = (size_t)(row + h * 8) * CDIM + col;
                if (p.mode == 3) {
                    *(float2*)(p.oF + o) = make_float2(v0, v1);
                } else if (p.mode == 2) {
                    *(uint32_t*)((__half*)p.oHi + o) = hf2pk(v1, v0);
                } else {   // mode 0
                    v0 = fmaxf(v0, 0.f); v1 = fmaxf(v1, 0.f);
                    uint32_t hp = bf2pk(v1, v0);
                    float e0 = __uint_as_float(hp << 16);
                    float e1 = __uint_as_float(hp & 0xffff0000u);
                    *(uint32_t*)(p.oHi + o) = hp;
                    *(uint32_t*)(p.oLo + o) = bf2pk(v1 - e1, v0 - e0);
                }
            }
        }
}

// ============================================================================
// split-K combine: X = bf16split(P0 + P1 + bias)
// ============================================================================
__global__ __launch_bounds__(256)
void combine_kernel(const float* __restrict__ P0, const float* __restrict__ P1,
                    const float* __restrict__ bias,
                    __nv_bfloat16* __restrict__ hi, __nv_bfloat16* __restrict__ lo) {
    int i = blockIdx.x * blockDim.x + threadIdx.x;      // float4 index
    float4 a = ((const float4*)P0)[i];
    float4 b = ((const float4*)P1)[i];
    int col = (i & (CDIM / 4 - 1)) * 4;
    float4 bv = *(const float4*)(bias + col);
    float f[4] = {a.x + b.x + bv.x, a.y + b.y + bv.y,
                  a.z + b.z + bv.z, a.w + b.w + bv.w};
    uint32_t hu[2], lu[2];
    #pragma unroll
    for (int j = 0; j < 2; j++) {
        uint32_t h = bf2pk(f[2*j+1], f[2*j]);
        float e0 = __uint_as_float(h << 16);
        float e1 = __uint_as_float(h & 0xffff0000u);
        hu[j] = h;
        lu[j] = bf2pk(f[2*j+1] - e1, f[2*j] - e0);
    }
    ((uint2*)hi)[i] = make_uint2(hu[0], hu[1]);
    ((uint2*)lo)[i] = make_uint2(lu[0], lu[1]);
}

// ============================================================================
// HMMA flash attention — V single fp16 (2-MMA O phase), 92KB smem
// ============================================================================
#define FP 144
#define QOFF(h)     ((h) * (128 * FP))
#define SOFF(s, t)  (2 * 128 * FP + (s) * (3 * 64 * FP) + (t) * (64 * FP))
#define FLASH_SMEM  (2 * 128 * FP + 2 * 3 * 64 * FP)   // 92160 B
#define SCL8_LOG2E  0.1803368801111204f                 // 0.125 * log2(e)

__global__ __launch_bounds__(256)
void flash_hmma(const __nv_bfloat16* __restrict__ Xh, const __nv_bfloat16* __restrict__ Xl,
                const __half* __restrict__ Vh,
                const float* __restrict__ LI, const float* __restrict__ bout,
                float* __restrict__ out) {
    extern __shared__ char smc[];
    const uint32_t sb = smem_u32(smc);
    const int tid = threadIdx.x;
    const int wid = tid >> 5, lane = tid & 31;
    const int g = lane >> 2, th = lane & 3;
    const int n0 = blockIdx.x * 128;
    const int grp = blockIdx.y;
    const size_t gcol = (size_t)grp * DH;

    const void* kvsrc[3] = {Xh, Xl, Vh};

    #pragma unroll
    for (int i = 0; i < 8; i++) {
        int id = tid + i * 256;
        int t = id >> 10, rem = id & 1023;
        int r = rem >> 3, q = rem & 7;
        const char* src = (const char*)((t ? Xl : Xh) + (size_t)(n0 + r) * CDIM + gcol) + q * 16;
        CP16(sb + QOFF(t) + r * FP + q * 16, src);
    }
    auto cp_kv = [&](int it, int s) {
        const int m0 = it * 64;
        #pragma unroll
        for (int i = 0; i < 6; i++) {
            int id = tid + i * 256;                    // 0..1535
            int t = id >> 9, rem = id & 511;
            int r = rem >> 3, q = rem & 7;
            uint32_t dst = sb + SOFF(s, t) + r * FP + q * 16;
            const char* src = (const char*)kvsrc[t] + ((size_t)(m0 + r) * CDIM + gcol) * 2 + q * 16;
            CP16(dst, src);
        }
    };

    cp_kv(0, 0);
    CP_COMMIT();
    CP_WAIT(0);
    __syncthreads();

    uint32_t qa[2][4][4];
    #pragma unroll
    for (int h = 0; h < 2; h++)
        #pragma unroll
        for (int kt = 0; kt < 4; kt++) {
            uint32_t ad = sb + QOFF(h) + (wid * 16 + (lane & 15)) * FP
                        + (kt * 16 + (lane >> 4) * 8) * 2;
            LDSM4(qa[h][kt], ad);
        }

    float accO[8][4] = {};
    float mi0 = -CUDART_INF_F, mi1 = -CUDART_INF_F;
    float ls0 = 0.f, ls1 = 0.f;

    const float* lbase = LI + (size_t)(n0 + wid * 16 + g) * NROI + 2 * th;

    for (int it = 0; it < 32; it++) {
        const int s = it & 1;

        float2 liA[8], liB[8];
        {
            const float* lp = lbase + it * 64;
            #pragma unroll
            for (int nt = 0; nt < 8; nt++) {
                liA[nt] = *(const float2*)(lp + nt * 8);
                liB[nt] = *(const float2*)(lp + 8 * NROI + nt * 8);
            }
        }

        if (it < 31) { cp_kv(it + 1, s ^ 1); CP_COMMIT(); CP_WAIT(1); }
        else         { CP_WAIT(0); }
        __syncthreads();

        const uint32_t stK = sb + SOFF(s, 0);
        const uint32_t stV = sb + SOFF(s, 2);

        float accS[8][4] = {};
        #pragma unroll
        for (int kt = 0; kt < 4; kt++) {
            uint32_t kh[4][4], kl[4][4];
            #pragma unroll
            for (int p = 0; p < 4; p++) {
                uint32_t ad = stK + (p * 16 + (lane & 15)) * FP
                            + (kt * 16 + (lane >> 4) * 8) * 2;
                LDSM4(kh[p], ad);
                LDSM4(kl[p], ad + 64 * FP);
            }
            #pragma unroll
            for (int p = 0; p < 4; p++) {
                uint32_t b0h[2] = {kh[p][0], kh[p][2]}, b1h[2] = {kh[p][1], kh[p][3]};
                uint32_t b0l[2] = {kl[p][0], kl[p][2]}, b1l[2] = {kl[p][1], kl[p][3]};
                MMA_BF16(accS[2*p],   qa[0][kt], b0h);
                MMA_BF16(accS[2*p],   qa[0][kt], b0l);
                MMA_BF16(accS[2*p],   qa[1][kt], b0h);
                MMA_BF16(accS[2*p+1], qa[0][kt], b1h);
                MMA_BF16(accS[2*p+1], qa[0][kt], b1l);
                MMA_BF16(accS[2*p+1], qa[1][kt], b1h);
            }
        }

        #pragma unroll
        for (int nt = 0; nt < 8; nt++) {
            accS[nt][0] = fmaf(accS[nt][0], SCL8_LOG2E, liA[nt].x);
            accS[nt][1] = fmaf(accS[nt][1], SCL8_LOG2E, liA[nt].y);
            accS[nt][2] = fmaf(accS[nt][2], SCL8_LOG2E, liB[nt].x);
            accS[nt][3] = fmaf(accS[nt][3], SCL8_LOG2E, liB[nt].y);
        }

        float mt0 = -CUDART_INF_F, mt1 = -CUDART_INF_F;
        #pragma unroll
        for (int nt = 0; nt < 8; nt++) {
            mt0 = fmaxf(mt0, fmaxf(accS[nt][0], accS[nt][1]));
            mt1 = fmaxf(mt1, fmaxf(accS[nt][2], accS[nt][3]));
        }
        mt0 = fmaxf(mt0, __shfl_xor_sync(0xffffffffu, mt0, 1));
        mt0 = fmaxf(mt0, __shfl_xor_sync(0xffffffffu, mt0, 2));
        mt1 = fmaxf(mt1, __shfl_xor_sync(0xffffffffu, mt1, 1));
        mt1 = fmaxf(mt1, __shfl_xor_sync(0xffffffffu, mt1, 2));
        float mn0 = fmaxf(mi0, mt0), mn1 = fmaxf(mi1, mt1);
        float al0 = ex2f(mi0 - mn0), al1 = ex2f(mi1 - mn1);
        mi0 = mn0; mi1 = mn1;

        uint32_t pa[4][4];
        float rs0 = 0.f, rs1 = 0.f;
        #pragma unroll
        for (int nt = 0; nt < 8; nt++) {
            float p0 = ex2f(accS[nt][0] - mn0 + 10.f);
            float p1 = ex2f(accS[nt][1] - mn0 + 10.f);
            float p2 = ex2f(accS[nt][2] - mn1 + 10.f);
            float p3 = ex2f(accS[nt][3] - mn1 + 10.f);
            rs0 += p0 + p1; rs1 += p2 + p3;
            int kt = nt >> 1, off = (nt & 1) * 2;
            pa[kt][off]     = hf2pk(p1, p0);
            pa[kt][off + 1] = hf2pk(p3, p2);
        }
        rs0 += __shfl_xor_sync(0xffffffffu, rs0, 1);
        rs0 += __shfl_xor_sync(0xffffffffu, rs0, 2);
        rs1 += __shfl_xor_sync(0xffffffffu, rs1, 1);
        rs1 += __shfl_xor_sync(0xffffffffu, rs1, 2);
        ls0 = ls0 * al0 + rs0;
        ls1 = ls1 * al1 + rs1;

        #pragma unroll
        for (int nt = 0; nt < 8; nt++) {
            accO[nt][0] *= al0; accO[nt][1] *= al0;
            accO[nt][2] *= al1; accO[nt][3] *= al1;
        }

        // ---- O += P V (single fp16 V: 2 MMAs per 16x16 block) ----
        #pragma unroll
        for (int kt = 0; kt < 4; kt++) {
            #pragma unroll
            for (int db = 0; db < 4; db++) {
                uint32_t vh[4];
                uint32_t ad = stV + (kt * 16 + (lane & 15)) * FP
                            + (db * 16 + (lane >> 4) * 8) * 2;
                LDSM4T(vh, ad);
                uint32_t bh0[2] = {vh[0], vh[1]}, bh1[2] = {vh[2], vh[3]};
                MMA_F16(accO[2*db],   pa[kt], bh0);
                MMA_F16(accO[2*db+1], pa[kt], bh1);
            }
        }
        __syncthreads();
    }

    const float inv0 = 1.f / ls0, inv1 = 1.f / ls1;
    #pragma unroll
    for (int nt = 0; nt < 8; nt++) {
        const int col = grp * DH + nt * 8 + 2 * th;
        float2 bo = *(const float2*)(bout + col);
        const int row = n0 + wid * 16 + g;
        *(float2*)(out + (size_t)row * CDIM + col) =
            make_float2(accO[nt][0] * inv0 + bo.x, accO[nt][1] * inv0 + bo.y);
        *(float2*)(out + (size_t)(row + 8) * CDIM + col) =
            make_float2(accO[nt][2] * inv1 + bo.x, accO[nt][3] * inv1 + bo.y);
    }
}

// ============================================================================
// launch
// ============================================================================
extern "C" void kernel_launch(void* const* d_in, const int* in_sizes, int n_in,
                              void* d_out, int out_size) {
    const float* in_x = (const float*)d_in[0];
    const float* rois = (const float*)d_in[1];
    const float* W0   = (const float*)d_in[2];
    const float* b0   = (const float*)d_in[3];
    const float* W1   = (const float*)d_in[4];
    const float* b1   = (const float*)d_in[5];
    const float* Wout = (const float*)d_in[6];
    const float* bout = (const float*)d_in[7];
    float* out = (float*)d_out;

    void *pA0h,*pA0l,*pA1h,*pA1l,*pA2h,*pA2l,*pW0h,*pW0l,*pW1h,*pW1l,*pWph,*pWpl;
    void *pXh,*pXl,*pVh,*pLI,*pPt0,*pPt1;
    cudaGetSymbolAddress(&pA0h, g_A0h); cudaGetSymbolAddress(&pA0l, g_A0l);
    cudaGetSymbolAddress(&pA1h, g_A1h); cudaGetSymbolAddress(&pA1l, g_A1l);
    cudaGetSymbolAddress(&pA2h, g_A2h); cudaGetSymbolAddress(&pA2l, g_A2l);
    cudaGetSymbolAddress(&pW0h, g_W0h); cudaGetSymbolAddress(&pW0l, g_W0l);
    cudaGetSymbolAddress(&pW1h, g_W1h); cudaGetSymbolAddress(&pW1l, g_W1l);
    cudaGetSymbolAddress(&pWph, g_Wph); cudaGetSymbolAddress(&pWpl, g_Wpl);
    cudaGetSymbolAddress(&pXh, g_Xh);   cudaGetSymbolAddress(&pXl, g_Xl);
    cudaGetSymbolAddress(&pVh, g_Vh);
    cudaGetSymbolAddress(&pPt0, g_Pt0); cudaGetSymbolAddress(&pPt1, g_Pt1);
    cudaGetSymbolAddress(&pLI, g_LI);

    // merged splits + logiou (independent per-block work)
    prep_all<<<7168 + 16384, 256>>>(in_x, W0, W1, Wout, rois, (float*)pLI,
                                    (__nv_bfloat16*)pA0h, (__nv_bfloat16*)pA0l,
                                    (__nv_bfloat16*)pA2h, (__nv_bfloat16*)pA2l,
                                    (__nv_bfloat16*)pW0h, (__nv_bfloat16*)pW0l,
                                    (__nv_bfloat16*)pW1h, (__nv_bfloat16*)pW1l,
                                    (__nv_bfloat16*)pWph, (__nv_bfloat16*)pWpl);

    cudaFuncSetAttribute(gemm_tc, cudaFuncAttributeMaxDynamicSharedMemorySize, GEMM_SMEM);

    // GEMM0 (mode0) ∥ GEMM2 (mode2): 256 CTAs, one co-resident wave
    GP g0 = {(__nv_bfloat16*)pA0h, (__nv_bfloat16*)pA0l,
             (__nv_bfloat16*)pW0h, (__nv_bfloat16*)pW0l,
             b0, (__nv_bfloat16*)pA1h, (__nv_bfloat16*)pA1l, nullptr, 0, 32, 0};
    GP g2 = {(__nv_bfloat16*)pA2h, (__nv_bfloat16*)pA2l,
             (__nv_bfloat16*)pWph, (__nv_bfloat16*)pWpl,
             nullptr, (__nv_bfloat16*)pVh, nullptr, nullptr, 0, 32, 2};
    gemm_tc<<<dim3(CDIM / 128, NROI / 128, 2), 256, GEMM_SMEM>>>(g0, g2);

    // GEMM1 split-K=2 (mode3 partials): 256 CTAs, one wave
    GP g1a = {(__nv_bfloat16*)pA1h, (__nv_bfloat16*)pA1l,
              (__nv_bfloat16*)pW1h, (__nv_bfloat16*)pW1l,
              nullptr, nullptr, nullptr, (float*)pPt0, 0, 16, 3};
    GP g1b = {(__nv_bfloat16*)pA1h, (__nv_bfloat16*)pA1l,
              (__nv_bfloat16*)pW1h, (__nv_bfloat16*)pW1l,
              nullptr, nullptr, nullptr, (float*)pPt1, 16, 16, 3};
    gemm_tc<<<dim3(CDIM / 128, NROI / 128, 2), 256, GEMM_SMEM>>>(g1a, g1b);

    // combine partials -> X (bf16 split)
    combine_kernel<<<(NROI * CDIM / 4) / 256, 256>>>((float*)pPt0, (float*)pPt1, b1,
                                                     (__nv_bfloat16*)pXh, (__nv_bfloat16*)pXl);

    // HMMA flash attention (V single fp16)
    cudaFuncSetAttribute(flash_hmma, cudaFuncAttributeMaxDynamicSharedMemorySize, FLASH_SMEM);
    flash_hmma<<<dim3(NROI / 128, GRP), 256, FLASH_SMEM>>>(
        (__nv_bfloat16*)pXh, (__nv_bfloat16*)pXl,
        (__half*)pVh, (float*)pLI, bout, out);
}

// round 14
// speedup vs baseline: 1.9134x; 1.1353x over previous
#include <cuda_runtime.h>
#include <cuda_bf16.h>
#include <cuda_fp16.h>
#include <math_constants.h>
#include <cstdint>

#define NROI 2048
#define CDIM 1024
#define GRP  16
#define DH   64

// ============================================================================
// device scratch
// ============================================================================
__device__ __nv_bfloat16 g_A0h[NROI * CDIM], g_A0l[NROI * CDIM];   // split relu(in_x)
__device__ __nv_bfloat16 g_A1h[NROI * CDIM], g_A1l[NROI * CDIM];   // split relu(H0)
__device__ __nv_bfloat16 g_A2h[NROI * CDIM], g_A2l[NROI * CDIM];   // split in_x
__device__ __nv_bfloat16 g_W0h[CDIM * CDIM], g_W0l[CDIM * CDIM];
__device__ __nv_bfloat16 g_W1h[CDIM * CDIM], g_W1l[CDIM * CDIM];
__device__ __nv_bfloat16 g_Wph[CDIM * CDIM], g_Wpl[CDIM * CDIM];
__device__ __half g_Xh[NROI * CDIM], g_Xl[NROI * CDIM];            // embedded X (Q/K), fp16 split
__device__ __half g_Vh[NROI * CDIM];                                // V, single fp16
__device__ float g_Pt0[NROI * CDIM], g_Pt1[NROI * CDIM];           // split-K partials (GEMM1)
__device__ float g_LI[NROI * NROI];                                 // log2(iou + 1e-6)

// ============================================================================
// PTX helpers
// ============================================================================
__device__ __forceinline__ uint32_t smem_u32(const void* p) {
    uint32_t a;
    asm("{ .reg .u64 t; cvta.to.shared.u64 t, %1; cvt.u32.u64 %0, t; }" : "=r"(a) : "l"(p));
    return a;
}
#define LDSM4(r, addr) \
    asm volatile("ldmatrix.sync.aligned.m8n8.x4.shared.b16 {%0,%1,%2,%3}, [%4];" \
        : "=r"((r)[0]), "=r"((r)[1]), "=r"((r)[2]), "=r"((r)[3]) : "r"(addr))
#define LDSM4T(r, addr) \
    asm volatile("ldmatrix.sync.aligned.m8n8.x4.trans.shared.b16 {%0,%1,%2,%3}, [%4];" \
        : "=r"((r)[0]), "=r"((r)[1]), "=r"((r)[2]), "=r"((r)[3]) : "r"(addr))
#define LDSM2(r, addr) \
    asm volatile("ldmatrix.sync.aligned.m8n8.x2.shared.b16 {%0,%1}, [%2];" \
        : "=r"((r)[0]), "=r"((r)[1]) : "r"(addr))
#define MMA_BF16(c, a, b) \
    asm volatile("mma.sync.aligned.m16n8k16.row.col.f32.bf16.bf16.f32 " \
        "{%0,%1,%2,%3}, {%4,%5,%6,%7}, {%8,%9}, {%0,%1,%2,%3};" \
        : "+f"((c)[0]), "+f"((c)[1]), "+f"((c)[2]), "+f"((c)[3]) \
        : "r"((a)[0]), "r"((a)[1]), "r"((a)[2]), "r"((a)[3]), "r"((b)[0]), "r"((b)[1]))
#define MMA_F16(c, a, b) \
    asm volatile("mma.sync.aligned.m16n8k16.row.col.f32.f16.f16.f32 " \
        "{%0,%1,%2,%3}, {%4,%5,%6,%7}, {%8,%9}, {%0,%1,%2,%3};" \
        : "+f"((c)[0]), "+f"((c)[1]), "+f"((c)[2]), "+f"((c)[3]) \
        : "r"((a)[0]), "r"((a)[1]), "r"((a)[2]), "r"((a)[3]), "r"((b)[0]), "r"((b)[1]))
#define CP16(dst, src)  asm volatile("cp.async.cg.shared.global [%0], [%1], 16;" :: "r"(dst), "l"(src))
#define CP_COMMIT()     asm volatile("cp.async.commit_group;" ::: "memory")
#define CP_WAIT(n)      asm volatile("cp.async.wait_group %0;" :: "n"(n) : "memory")

__device__ __forceinline__ uint32_t bf2pk(float hi, float lo) {
    uint32_t r; asm("cvt.rn.bf16x2.f32 %0, %1, %2;" : "=r"(r) : "f"(hi), "f"(lo)); return r;
}
__device__ __forceinline__ uint32_t hf2pk(float hi, float lo) {
    uint32_t r; asm("cvt.rn.f16x2.f32 %0, %1, %2;" : "=r"(r) : "f"(hi), "f"(lo)); return r;
}
__device__ __forceinline__ float ex2f(float x) {
    float r; asm("ex2.approx.f32 %0, %1;" : "=f"(r) : "f"(x)); return r;
}

// ============================================================================
// merged prep kernel: 5 split segments + log2-IoU table, one launch
// ============================================================================
__global__ __launch_bounds__(256)
void prep_all(const float* __restrict__ in_x, const float* __restrict__ W0,
              const float* __restrict__ W1, const float* __restrict__ Wp,
              const float* __restrict__ rois, float* __restrict__ li,
              __nv_bfloat16* __restrict__ a0h, __nv_bfloat16* __restrict__ a0l,
              __nv_bfloat16* __restrict__ a2h, __nv_bfloat16* __restrict__ a2l,
              __nv_bfloat16* __restrict__ w0h, __nv_bfloat16* __restrict__ w0l,
              __nv_bfloat16* __restrict__ w1h, __nv_bfloat16* __restrict__ w1l,
              __nv_bfloat16* __restrict__ wph, __nv_bfloat16* __restrict__ wpl) {
    const int b = blockIdx.x;
    if (b >= 7168) {                       // ---- log-IoU segment ----
        int idx = (b - 7168) * 256 + threadIdx.x;
        int n = idx >> 11;
        int m = idx & 2047;
        const float* a = rois + n * 5 + 1;
        const float* bb = rois + m * 5 + 1;
        float ax1 = a[0], ay1 = a[1], ax2 = a[2], ay2 = a[3];
        float bx1 = bb[0], by1 = bb[1], bx2 = bb[2], by2 = bb[3];
        float areaA = (ax2 - ax1 + 1.f) * (ay2 - ay1 + 1.f);
        float areaB = (bx2 - bx1 + 1.f) * (by2 - by1 + 1.f);
        float w = fminf(ax2, bx2) - fmaxf(ax1, bx1) + 1.f; w = fmaxf(w, 0.f);
        float h = fminf(ay2, by2) - fmaxf(ay1, by1) + 1.f; h = fmaxf(h, 0.f);
        float inter = w * h;
        float iou = __fdividef(inter, areaA + areaB - inter);
        li[idx] = __log2f(iou + 1e-6f);
        return;
    }
    const float* src; __nv_bfloat16 *hi, *lo; int relu = 0, base;
    if      (b < 2048) { src = in_x; hi = a0h; lo = a0l; relu = 1; base = 0; }
    else if (b < 4096) { src = in_x; hi = a2h; lo = a2l; base = 2048; }
    else if (b < 5120) { src = W0;   hi = w0h; lo = w0l; base = 4096; }
    else if (b < 6144) { src = W1;   hi = w1h; lo = w1l; base = 5120; }
    else               { src = Wp;   hi = wph; lo = wpl; base = 6144; }
    int i = (b - base) * 256 + threadIdx.x;
    float4 v = ((const float4*)src)[i];
    if (relu) {
        v.x = fmaxf(v.x, 0.f); v.y = fmaxf(v.y, 0.f);
        v.z = fmaxf(v.z, 0.f); v.w = fmaxf(v.w, 0.f);
    }
    float f[4] = {v.x, v.y, v.z, v.w};
    uint32_t hu[2], lu[2];
    #pragma unroll
    for (int j = 0; j < 2; j++) {
        uint32_t h = bf2pk(f[2*j+1], f[2*j]);
        float e0 = __uint_as_float(h << 16);
        float e1 = __uint_as_float(h & 0xffff0000u);
        hu[j] = h;
        lu[j] = bf2pk(f[2*j+1] - e1, f[2*j] - e0);
    }
    ((uint2*)hi)[i] = make_uint2(hu[0], hu[1]);
    ((uint2*)lo)[i] = make_uint2(lu[0], lu[1]);
}

// ============================================================================
// HMMA split-bf16 GEMM, 128x128 tile, dual-problem via gridDim.z
//   mode 0: relu(acc+bias)->bf16 split    mode 2: acc->single fp16
//   mode 3: acc->fp32 partial (split-K)
// ============================================================================
struct GP {
    const __nv_bfloat16 *Ah, *Al, *Bh, *Bl;
    const float* bias;
    __nv_bfloat16 *oHi, *oLo;
    float* oF;
    int kStart, nChunks, mode;
};

#define TILE_BYTES  10240            // 128 rows x 80 B
#define STAGE_BYTES (4 * TILE_BYTES)
#define GEMM_SMEM   (2 * STAGE_BYTES)  // 81920

__global__ __launch_bounds__(256, 2)
void gemm_tc(GP p0, GP p1) {
    const GP p = (blockIdx.z == 0) ? p0 : p1;
    extern __shared__ char smc[];
    const uint32_t sb = smem_u32(smc);
    const int tid = threadIdx.x;
    const int wid = tid >> 5, lane = tid & 31;
    const int wm = wid & 1, wn = wid >> 1;
    const int row0 = blockIdx.y * 128;
    const int col0 = blockIdx.x * 128;

    const __nv_bfloat16* srcs[4] = {p.Ah, p.Al, p.Bh, p.Bl};

    auto cp_chunk = [&](int c, int s) {
        const int kb = (p.kStart + c) * 32;
        #pragma unroll
        for (int t = 0; t < 4; t++) {
            const char* src = (const char*)(srcs[t] + (size_t)((t < 2) ? row0 : col0) * CDIM + kb);
            uint32_t dst = sb + s * STAGE_BYTES + t * TILE_BYTES;
            #pragma unroll
            for (int i = 0; i < 2; i++) {
                int id = tid + i * 256;
                int r = id >> 2, q = id & 3;
                CP16(dst + r * 80 + q * 16, src + (size_t)r * (CDIM * 2) + q * 16);
            }
        }
    };

    float acc[4][4][4] = {};
    cp_chunk(0, 0); CP_COMMIT();

    const int NC = p.nChunks;
    for (int c = 0; c < NC; c++) {
        const int s = c & 1;
        if (c < NC - 1) { cp_chunk(c + 1, s ^ 1); CP_COMMIT(); CP_WAIT(1); }
        else            { CP_WAIT(0); }
        __syncthreads();

        const uint32_t stg = sb + s * STAGE_BYTES;
        #pragma unroll
        for (int ks = 0; ks < 2; ks++) {
            uint32_t ah[4][4], al[4][4], bh[4][2], bl[4][2];
            {
                const int kk = ks * 16 + (lane >> 4) * 8;
                #pragma unroll
                for (int mt = 0; mt < 4; mt++) {
                    const int ra = wm * 64 + mt * 16 + (lane & 15);
                    uint32_t ad = stg + ra * 80 + kk * 2;
                    LDSM4(ah[mt], ad);
                    LDSM4(al[mt], ad + TILE_BYTES);
                }
            }
            {
                const int kk = ks * 16 + ((lane >> 3) & 1) * 8;
                #pragma unroll
                for (int nt = 0; nt < 4; nt++) {
                    const int rb = wn * 32 + nt * 8 + (lane & 7);
                    uint32_t bd = stg + 2 * TILE_BYTES + rb * 80 + kk * 2;
                    LDSM2(bh[nt], bd);
                    LDSM2(bl[nt], bd + TILE_BYTES);
                }
            }
            #pragma unroll
            for (int mt = 0; mt < 4; mt++)
                #pragma unroll
                for (int nt = 0; nt < 4; nt++) {
                    MMA_BF16(acc[mt][nt], ah[mt], bh[nt]);
                    MMA_BF16(acc[mt][nt], ah[mt], bl[nt]);
                    MMA_BF16(acc[mt][nt], al[mt], bh[nt]);
                }
        }
        __syncthreads();
    }

    const int g = lane >> 2, th = lane & 3;
    #pragma unroll
    for (int mt = 0; mt < 4; mt++)
        #pragma unroll
        for (int nt = 0; nt < 4; nt++) {
            const int row = row0 + wm * 64 + mt * 16 + g;
            const int col = col0 + wn * 32 + nt * 8 + th * 2;
            float2 bv = make_float2(0.f, 0.f);
            if (p.mode == 0) bv = *(const float2*)(p.bias + col);
            const float* cc = acc[mt][nt];
            #pragma unroll
            for (int h = 0; h < 2; h++) {
                float v0 = cc[h * 2 + 0] + bv.x;
                float v1 = cc[h * 2 + 1] + bv.y;
                size_t o = (size_t)(row + h * 8) * CDIM + col;
                if (p.mode == 3) {
                    *(float2*)(p.oF + o) = make_float2(v0, v1);
                } else if (p.mode == 2) {
                    *(uint32_t*)((__half*)p.oHi + o) = hf2pk(v1, v0);
                } else {   // mode 0
                    v0 = fmaxf(v0, 0.f); v1 = fmaxf(v1, 0.f);
                    uint32_t hp = bf2pk(v1, v0);
                    float e0 = __uint_as_float(hp << 16);
                    float e1 = __uint_as_float(hp & 0xffff0000u);
                    *(uint32_t*)(p.oHi + o) = hp;
                    *(uint32_t*)(p.oLo + o) = bf2pk(v1 - e1, v0 - e0);
                }
            }
        }
}

// ============================================================================
// split-K combine: X = fp16split(P0 + P1 + bias)  (fp16 hi/lo for flash Q/K)
// ============================================================================
__global__ __launch_bounds__(256)
void combine_kernel(const float* __restrict__ P0, const float* __restrict__ P1,
                    const float* __restrict__ bias,
                    __half* __restrict__ hi, __half* __restrict__ lo) {
    int i = blockIdx.x * blockDim.x + threadIdx.x;      // float4 index
    float4 a = ((const float4*)P0)[i];
    float4 b = ((const float4*)P1)[i];
    int col = (i & (CDIM / 4 - 1)) * 4;
    float4 bv = *(const float4*)(bias + col);
    float f[4] = {a.x + b.x + bv.x, a.y + b.y + bv.y,
                  a.z + b.z + bv.z, a.w + b.w + bv.w};
    uint32_t hu[2], lu[2];
    #pragma unroll
    for (int j = 0; j < 2; j++) {
        uint32_t h = hf2pk(f[2*j+1], f[2*j]);
        __half2 hh = *(__half2*)&h;
        float2 e = __half22float2(hh);          // e.x = lo half, e.y = hi half
        hu[j] = h;
        lu[j] = hf2pk(f[2*j+1] - e.y, f[2*j] - e.x);
    }
    ((uint2*)hi)[i] = make_uint2(hu[0], hu[1]);
    ((uint2*)lo)[i] = make_uint2(lu[0], lu[1]);
}

// ============================================================================
// HMMA flash attention — fp16 2-MMA S phase (Q = Xh only, K = Xh+Xl),
// single-fp16 V (2-MMA O phase). 72KB smem, 96 MMAs/warp/iter.
// ============================================================================
#define FP 144
#define SOFF(s, t)  (128 * FP + (s) * (3 * 64 * FP) + (t) * (64 * FP))
#define FLASH_SMEM  (128 * FP + 2 * 3 * 64 * FP)       // 73728 B
#define SCL8_LOG2E  0.1803368801111204f                 // 0.125 * log2(e)

__global__ __launch_bounds__(256)
void flash_hmma(const __half* __restrict__ Xh, const __half* __restrict__ Xl,
                const __half* __restrict__ Vh,
                const float* __restrict__ LI, const float* __restrict__ bout,
                float* __restrict__ out) {
    extern __shared__ char smc[];
    const uint32_t sb = smem_u32(smc);
    const int tid = threadIdx.x;
    const int wid = tid >> 5, lane = tid & 31;
    const int g = lane >> 2, th = lane & 3;
    const int n0 = blockIdx.x * 128;
    const int grp = blockIdx.y;
    const size_t gcol = (size_t)grp * DH;

    const void* kvsrc[3] = {Xh, Xl, Vh};

    // ---- cp.async: Q hi only (128x64 fp16) once ----
    #pragma unroll
    for (int i = 0; i < 4; i++) {
        int id = tid + i * 256;                         // 0..1023
        int r = id >> 3, q = id & 7;
        const char* src = (const char*)(Xh + (size_t)(n0 + r) * CDIM + gcol) + q * 16;
        CP16(sb + r * FP + q * 16, src);
    }
    auto cp_kv = [&](int it, int s) {
        const int m0 = it * 64;
        #pragma unroll
        for (int i = 0; i < 6; i++) {
            int id = tid + i * 256;                     // 0..1535
            int t = id >> 9, rem = id & 511;
            int r = rem >> 3, q = rem & 7;
            uint32_t dst = sb + SOFF(s, t) + r * FP + q * 16;
            const char* src = (const char*)kvsrc[t] + ((size_t)(m0 + r) * CDIM + gcol) * 2 + q * 16;
            CP16(dst, src);
        }
    };

    cp_kv(0, 0);
    CP_COMMIT();
    CP_WAIT(0);
    __syncthreads();

    // ---- Q fragments (fp16, hi only) resident for all iterations ----
    uint32_t qa[4][4];
    #pragma unroll
    for (int kt = 0; kt < 4; kt++) {
        uint32_t ad = sb + (wid * 16 + (lane & 15)) * FP
                    + (kt * 16 + (lane >> 4) * 8) * 2;
        LDSM4(qa[kt], ad);
    }

    float accO[8][4] = {};
    float mi0 = -CUDART_INF_F, mi1 = -CUDART_INF_F;
    float ls0 = 0.f, ls1 = 0.f;

    const float* lbase = LI + (size_t)(n0 + wid * 16 + g) * NROI + 2 * th;

    for (int it = 0; it < 32; it++) {
        const int s = it & 1;

        float2 liA[8], liB[8];
        {
            const float* lp = lbase + it * 64;
            #pragma unroll
            for (int nt = 0; nt < 8; nt++) {
                liA[nt] = *(const float2*)(lp + nt * 8);
                liB[nt] = *(const float2*)(lp + 8 * NROI + nt * 8);
            }
        }

        if (it < 31) { cp_kv(it + 1, s ^ 1); CP_COMMIT(); CP_WAIT(1); }
        else         { CP_WAIT(0); }
        __syncthreads();

        const uint32_t stK = sb + SOFF(s, 0);
        const uint32_t stV = sb + SOFF(s, 2);

        // ---- S = Qh (Kh + Kl)^T : 2 fp16 MMAs per 16x16 block ----
        float accS[8][4] = {};
        #pragma unroll
        for (int kt = 0; kt < 4; kt++) {
            uint32_t kh[4][4], kl[4][4];
            #pragma unroll
            for (int p = 0; p < 4; p++) {
                uint32_t ad = stK + (p * 16 + (lane & 15)) * FP
                            + (kt * 16 + (lane >> 4) * 8) * 2;
                LDSM4(kh[p], ad);
                LDSM4(kl[p], ad + 64 * FP);
            }
            #pragma unroll
            for (int p = 0; p < 4; p++) {
                uint32_t b0h[2] = {kh[p][0], kh[p][2]}, b1h[2] = {kh[p][1], kh[p][3]};
                uint32_t b0l[2] = {kl[p][0], kl[p][2]}, b1l[2] = {kl[p][1], kl[p][3]};
                MMA_F16(accS[2*p],   qa[kt], b0h);
                MMA_F16(accS[2*p],   qa[kt], b0l);
                MMA_F16(accS[2*p+1], qa[kt], b1h);
                MMA_F16(accS[2*p+1], qa[kt], b1l);
            }
        }

        #pragma unroll
        for (int nt = 0; nt < 8; nt++) {
            accS[nt][0] = fmaf(accS[nt][0], SCL8_LOG2E, liA[nt].x);
            accS[nt][1] = fmaf(accS[nt][1], SCL8_LOG2E, liA[nt].y);
            accS[nt][2] = fmaf(accS[nt][2], SCL8_LOG2E, liB[nt].x);
            accS[nt][3] = fmaf(accS[nt][3], SCL8_LOG2E, liB[nt].y);
        }

        float mt0 = -CUDART_INF_F, mt1 = -CUDART_INF_F;
        #pragma unroll
        for (int nt = 0; nt < 8; nt++) {
            mt0 = fmaxf(mt0, fmaxf(accS[nt][0], accS[nt][1]));
            mt1 = fmaxf(mt1, fmaxf(accS[nt][2], accS[nt][3]));
        }
        mt0 = fmaxf(mt0, __shfl_xor_sync(0xffffffffu, mt0, 1));
        mt0 = fmaxf(mt0, __shfl_xor_sync(0xffffffffu, mt0, 2));
        mt1 = fmaxf(mt1, __shfl_xor_sync(0xffffffffu, mt1, 1));
        mt1 = fmaxf(mt1, __shfl_xor_sync(0xffffffffu, mt1, 2));
        float mn0 = fmaxf(mi0, mt0), mn1 = fmaxf(mi1, mt1);
        float al0 = ex2f(mi0 - mn0), al1 = ex2f(mi1 - mn1);
        mi0 = mn0; mi1 = mn1;

        uint32_t pa[4][4];
        float rs0 = 0.f, rs1 = 0.f;
        #pragma unroll
        for (int nt = 0; nt < 8; nt++) {
            float p0 = ex2f(accS[nt][0] - mn0 + 10.f);
            float p1 = ex2f(accS[nt][1] - mn0 + 10.f);
            float p2 = ex2f(accS[nt][2] - mn1 + 10.f);
            float p3 = ex2f(accS[nt][3] - mn1 + 10.f);
            rs0 += p0 + p1; rs1 += p2 + p3;
            int kt = nt >> 1, off = (nt & 1) * 2;
            pa[kt][off]     = hf2pk(p1, p0);
            pa[kt][off + 1] = hf2pk(p3, p2);
        }
        rs0 += __shfl_xor_sync(0xffffffffu, rs0, 1);
        rs0 += __shfl_xor_sync(0xffffffffu, rs0, 2);
        rs1 += __shfl_xor_sync(0xffffffffu, rs1, 1);
        rs1 += __shfl_xor_sync(0xffffffffu, rs1, 2);
        ls0 = ls0 * al0 + rs0;
        ls1 = ls1 * al1 + rs1;

        #pragma unroll
        for (int nt = 0; nt < 8; nt++) {
            accO[nt][0] *= al0; accO[nt][1] *= al0;
            accO[nt][2] *= al1; accO[nt][3] *= al1;
        }

        // ---- O += P V (single fp16 V) ----
        #pragma unroll
        for (int kt = 0; kt < 4; kt++) {
            #pragma unroll
            for (int db = 0; db < 4; db++) {
                uint32_t vh[4];
                uint32_t ad = stV + (kt * 16 + (lane & 15)) * FP
                            + (db * 16 + (lane >> 4) * 8) * 2;
                LDSM4T(vh, ad);
                uint32_t bh0[2] = {vh[0], vh[1]}, bh1[2] = {vh[2], vh[3]};
                MMA_F16(accO[2*db],   pa[kt], bh0);
                MMA_F16(accO[2*db+1], pa[kt], bh1);
            }
        }
        __syncthreads();
    }

    const float inv0 = 1.f / ls0, inv1 = 1.f / ls1;
    #pragma unroll
    for (int nt = 0; nt < 8; nt++) {
        const int col = grp * DH + nt * 8 + 2 * th;
        float2 bo = *(const float2*)(bout + col);
        const int row = n0 + wid * 16 + g;
        *(float2*)(out + (size_t)row * CDIM + col) =
            make_float2(accO[nt][0] * inv0 + bo.x, accO[nt][1] * inv0 + bo.y);
        *(float2*)(out + (size_t)(row + 8) * CDIM + col) =
            make_float2(accO[nt][2] * inv1 + bo.x, accO[nt][3] * inv1 + bo.y);
    }
}

// ============================================================================
// launch
// ============================================================================
extern "C" void kernel_launch(void* const* d_in, const int* in_sizes, int n_in,
                              void* d_out, int out_size) {
    const float* in_x = (const float*)d_in[0];
    const float* rois = (const float*)d_in[1];
    const float* W0   = (const float*)d_in[2];
    const float* b0   = (const float*)d_in[3];
    const float* W1   = (const float*)d_in[4];
    const float* b1   = (const float*)d_in[5];
    const float* Wout = (const float*)d_in[6];
    const float* bout = (const float*)d_in[7];
    float* out = (float*)d_out;

    void *pA0h,*pA0l,*pA1h,*pA1l,*pA2h,*pA2l,*pW0h,*pW0l,*pW1h,*pW1l,*pWph,*pWpl;
    void *pXh,*pXl,*pVh,*pLI,*pPt0,*pPt1;
    cudaGetSymbolAddress(&pA0h, g_A0h); cudaGetSymbolAddress(&pA0l, g_A0l);
    cudaGetSymbolAddress(&pA1h, g_A1h); cudaGetSymbolAddress(&pA1l, g_A1l);
    cudaGetSymbolAddress(&pA2h, g_A2h); cudaGetSymbolAddress(&pA2l, g_A2l);
    cudaGetSymbolAddress(&pW0h, g_W0h); cudaGetSymbolAddress(&pW0l, g_W0l);
    cudaGetSymbolAddress(&pW1h, g_W1h); cudaGetSymbolAddress(&pW1l, g_W1l);
    cudaGetSymbolAddress(&pWph, g_Wph); cudaGetSymbolAddress(&pWpl, g_Wpl);
    cudaGetSymbolAddress(&pXh, g_Xh);   cudaGetSymbolAddress(&pXl, g_Xl);
    cudaGetSymbolAddress(&pVh, g_Vh);
    cudaGetSymbolAddress(&pPt0, g_Pt0); cudaGetSymbolAddress(&pPt1, g_Pt1);
    cudaGetSymbolAddress(&pLI, g_LI);

    // merged splits + logiou
    prep_all<<<7168 + 16384, 256>>>(in_x, W0, W1, Wout, rois, (float*)pLI,
                                    (__nv_bfloat16*)pA0h, (__nv_bfloat16*)pA0l,
                                    (__nv_bfloat16*)pA2h, (__nv_bfloat16*)pA2l,
                                    (__nv_bfloat16*)pW0h, (__nv_bfloat16*)pW0l,
                                    (__nv_bfloat16*)pW1h, (__nv_bfloat16*)pW1l,
                                    (__nv_bfloat16*)pWph, (__nv_bfloat16*)pWpl);

    cudaFuncSetAttribute(gemm_tc, cudaFuncAttributeMaxDynamicSharedMemorySize, GEMM_SMEM);

    // GEMM0 (mode0) ∥ GEMM2 (mode2): 256 CTAs, one co-resident wave
    GP g0 = {(__nv_bfloat16*)pA0h, (__nv_bfloat16*)pA0l,
             (__nv_bfloat16*)pW0h, (__nv_bfloat16*)pW0l,
             b0, (__nv_bfloat16*)pA1h, (__nv_bfloat16*)pA1l, nullptr, 0, 32, 0};
    GP g2 = {(__nv_bfloat16*)pA2h, (__nv_bfloat16*)pA2l,
             (__nv_bfloat16*)pWph, (__nv_bfloat16*)pWpl,
             nullptr, (__nv_bfloat16*)pVh, nullptr, nullptr, 0, 32, 2};
    gemm_tc<<<dim3(CDIM / 128, NROI / 128, 2), 256, GEMM_SMEM>>>(g0, g2);

    // GEMM1 split-K=2 (mode3 partials): 256 CTAs, one wave
    GP g1a = {(__nv_bfloat16*)pA1h, (__nv_bfloat16*)pA1l,
              (__nv_bfloat16*)pW1h, (__nv_bfloat16*)pW1l,
              nullptr, nullptr, nullptr, (float*)pPt0, 0, 16, 3};
    GP g1b = {(__nv_bfloat16*)pA1h, (__nv_bfloat16*)pA1l,
              (__nv_bfloat16*)pW1h, (__nv_bfloat16*)pW1l,
              nullptr, nullptr, nullptr, (float*)pPt1, 16, 16, 3};
    gemm_tc<<<dim3(CDIM / 128, NROI / 128, 2), 256, GEMM_SMEM>>>(g1a, g1b);

    // combine partials -> X (fp16 split)
    combine_kernel<<<(NROI * CDIM / 4) / 256, 256>>>((float*)pPt0, (float*)pPt1, b1,
                                                     (__half*)pXh, (__half*)pXl);

    // HMMA flash attention (fp16 2-MMA S phase)
    cudaFuncSetAttribute(flash_hmma, cudaFuncAttributeMaxDynamicSharedMemorySize, FLASH_SMEM);
    flash_hmma<<<dim3(NROI / 128, GRP), 256, FLASH_SMEM>>>(
        (__half*)pXh, (__half*)pXl,
        (__half*)pVh, (float*)pLI, bout, out);
}

// round 15
// speedup vs baseline: 2.1526x; 1.1250x over previous
#include <cuda_runtime.h>
#include <cuda_bf16.h>
#include <cuda_fp16.h>
#include <math_constants.h>
#include <cstdint>

#define NROI 2048
#define CDIM 1024
#define GRP  16
#define DH   64

// ============================================================================
// device scratch
// ============================================================================
__device__ __half g_A0[NROI * CDIM];                    // relu(in_x), fp16 single
__device__ __half g_A1[NROI * CDIM];                    // relu(H0), fp16 single
__device__ __half g_A2[NROI * CDIM];                    // in_x, fp16 single
__device__ __half g_W0h[CDIM * CDIM], g_W0l[CDIM * CDIM];   // weights, fp16 hi/lo
__device__ __half g_W1h[CDIM * CDIM], g_W1l[CDIM * CDIM];
__device__ __half g_Wph[CDIM * CDIM], g_Wpl[CDIM * CDIM];
__device__ __half g_Xh[NROI * CDIM], g_Xl[NROI * CDIM]; // embedded X (Q/K), fp16 split
__device__ __half g_Vh[NROI * CDIM];                    // V, single fp16
__device__ float g_Pt0[NROI * CDIM], g_Pt1[NROI * CDIM];// split-K partials (GEMM1)
__device__ float g_LI[NROI * NROI];                     // log2(iou + 1e-6)

// ============================================================================
// PTX helpers
// ============================================================================
__device__ __forceinline__ uint32_t smem_u32(const void* p) {
    uint32_t a;
    asm("{ .reg .u64 t; cvta.to.shared.u64 t, %1; cvt.u32.u64 %0, t; }" : "=r"(a) : "l"(p));
    return a;
}
#define LDSM4(r, addr) \
    asm volatile("ldmatrix.sync.aligned.m8n8.x4.shared.b16 {%0,%1,%2,%3}, [%4];" \
        : "=r"((r)[0]), "=r"((r)[1]), "=r"((r)[2]), "=r"((r)[3]) : "r"(addr))
#define LDSM4T(r, addr) \
    asm volatile("ldmatrix.sync.aligned.m8n8.x4.trans.shared.b16 {%0,%1,%2,%3}, [%4];" \
        : "=r"((r)[0]), "=r"((r)[1]), "=r"((r)[2]), "=r"((r)[3]) : "r"(addr))
#define LDSM2(r, addr) \
    asm volatile("ldmatrix.sync.aligned.m8n8.x2.shared.b16 {%0,%1}, [%2];" \
        : "=r"((r)[0]), "=r"((r)[1]) : "r"(addr))
#define MMA_F16(c, a, b) \
    asm volatile("mma.sync.aligned.m16n8k16.row.col.f32.f16.f16.f32 " \
        "{%0,%1,%2,%3}, {%4,%5,%6,%7}, {%8,%9}, {%0,%1,%2,%3};" \
        : "+f"((c)[0]), "+f"((c)[1]), "+f"((c)[2]), "+f"((c)[3]) \
        : "r"((a)[0]), "r"((a)[1]), "r"((a)[2]), "r"((a)[3]), "r"((b)[0]), "r"((b)[1]))
#define CP16(dst, src)  asm volatile("cp.async.cg.shared.global [%0], [%1], 16;" :: "r"(dst), "l"(src))
#define CP_COMMIT()     asm volatile("cp.async.commit_group;" ::: "memory")
#define CP_WAIT(n)      asm volatile("cp.async.wait_group %0;" :: "n"(n) : "memory")

__device__ __forceinline__ uint32_t hf2pk(float hi, float lo) {
    uint32_t r; asm("cvt.rn.f16x2.f32 %0, %1, %2;" : "=r"(r) : "f"(hi), "f"(lo)); return r;
}
__device__ __forceinline__ float ex2f(float x) {
    float r; asm("ex2.approx.f32 %0, %1;" : "=f"(r) : "f"(x)); return r;
}

// ============================================================================
// merged prep kernel: activations -> fp16 single, weights -> fp16 hi/lo,
// plus log2-IoU table; one launch
// ============================================================================
__global__ __launch_bounds__(256)
void prep_all(const float* __restrict__ in_x, const float* __restrict__ W0,
              const float* __restrict__ W1, const float* __restrict__ Wp,
              const float* __restrict__ rois, float* __restrict__ li,
              __half* __restrict__ a0, __half* __restrict__ a2,
              __half* __restrict__ w0h, __half* __restrict__ w0l,
              __half* __restrict__ w1h, __half* __restrict__ w1l,
              __half* __restrict__ wph, __half* __restrict__ wpl) {
    const int b = blockIdx.x;
    if (b >= 7168) {                       // ---- log-IoU segment ----
        int idx = (b - 7168) * 256 + threadIdx.x;
        int n = idx >> 11;
        int m = idx & 2047;
        const float* a = rois + n * 5 + 1;
        const float* bb = rois + m * 5 + 1;
        float ax1 = a[0], ay1 = a[1], ax2 = a[2], ay2 = a[3];
        float bx1 = bb[0], by1 = bb[1], bx2 = bb[2], by2 = bb[3];
        float areaA = (ax2 - ax1 + 1.f) * (ay2 - ay1 + 1.f);
        float areaB = (bx2 - bx1 + 1.f) * (by2 - by1 + 1.f);
        float w = fminf(ax2, bx2) - fmaxf(ax1, bx1) + 1.f; w = fmaxf(w, 0.f);
        float h = fminf(ay2, by2) - fmaxf(ay1, by1) + 1.f; h = fmaxf(h, 0.f);
        float inter = w * h;
        float iou = __fdividef(inter, areaA + areaB - inter);
        li[idx] = __log2f(iou + 1e-6f);
        return;
    }
    if (b < 4096) {                        // ---- activations: fp16 single ----
        const float* src = in_x;
        __half* dst = (b < 2048) ? a0 : a2;
        int relu = (b < 2048);
        int i = (b & 2047) * 256 + threadIdx.x;
        float4 v = ((const float4*)src)[i];
        if (relu) {
            v.x = fmaxf(v.x, 0.f); v.y = fmaxf(v.y, 0.f);
            v.z = fmaxf(v.z, 0.f); v.w = fmaxf(v.w, 0.f);
        }
        ((uint2*)dst)[i] = make_uint2(hf2pk(v.y, v.x), hf2pk(v.w, v.z));
        return;
    }
    // ---- weights: fp16 hi/lo split ----
    const float* src; __half *hi, *lo; int base;
    if      (b < 5120) { src = W0; hi = w0h; lo = w0l; base = 4096; }
    else if (b < 6144) { src = W1; hi = w1h; lo = w1l; base = 5120; }
    else               { src = Wp; hi = wph; lo = wpl; base = 6144; }
    int i = (b - base) * 256 + threadIdx.x;
    float4 v = ((const float4*)src)[i];
    float f[4] = {v.x, v.y, v.z, v.w};
    uint32_t hu[2], lu[2];
    #pragma unroll
    for (int j = 0; j < 2; j++) {
        uint32_t h = hf2pk(f[2*j+1], f[2*j]);
        __half2 hh = *(__half2*)&h;
        float2 e = __half22float2(hh);
        hu[j] = h;
        lu[j] = hf2pk(f[2*j+1] - e.y, f[2*j] - e.x);
    }
    ((uint2*)hi)[i] = make_uint2(hu[0], hu[1]);
    ((uint2*)lo)[i] = make_uint2(lu[0], lu[1]);
}

// ============================================================================
// HMMA fp16 2-MMA GEMM, 128x128 tile, dual-problem via gridDim.z
//   acc = A (Bh + Bl)^T;  A single fp16, B fp16 hi/lo
//   mode 0: relu(acc+bias) -> fp16     mode 2: acc -> fp16
//   mode 3: acc -> fp32 partial (split-K)
// ============================================================================
struct GP {
    const __half *A, *Bh, *Bl;
    const float* bias;
    __half* oH;
    float* oF;
    int kStart, nChunks, mode;
};

#define TILE_BYTES  10240            // 128 rows x 80 B
#define STAGE_BYTES (3 * TILE_BYTES) // A, Bh, Bl
#define GEMM_SMEM   (2 * STAGE_BYTES)  // 61440

__global__ __launch_bounds__(256, 2)
void gemm_tc(GP p0, GP p1) {
    const GP p = (blockIdx.z == 0) ? p0 : p1;
    extern __shared__ char smc[];
    const uint32_t sb = smem_u32(smc);
    const int tid = threadIdx.x;
    const int wid = tid >> 5, lane = tid & 31;
    const int wm = wid & 1, wn = wid >> 1;
    const int row0 = blockIdx.y * 128;
    const int col0 = blockIdx.x * 128;

    const __half* srcs[3] = {p.A, p.Bh, p.Bl};

    auto cp_chunk = [&](int c, int s) {
        const int kb = (p.kStart + c) * 32;
        #pragma unroll
        for (int i = 0; i < 6; i++) {
            int id = tid + i * 256;                    // 0..1535
            int t = id >> 9, rem = id & 511;
            int r = rem >> 2, q = rem & 3;
            const char* src = (const char*)(srcs[t] + (size_t)((t == 0 ? row0 : col0) + r) * CDIM + kb) + q * 16;
            CP16(sb + s * STAGE_BYTES + t * TILE_BYTES + r * 80 + q * 16, src);
        }
    };

    float acc[4][4][4] = {};
    cp_chunk(0, 0); CP_COMMIT();

    const int NC = p.nChunks;
    for (int c = 0; c < NC; c++) {
        const int s = c & 1;
        if (c < NC - 1) { cp_chunk(c + 1, s ^ 1); CP_COMMIT(); CP_WAIT(1); }
        else            { CP_WAIT(0); }
        __syncthreads();

        const uint32_t stg = sb + s * STAGE_BYTES;
        #pragma unroll
        for (int ks = 0; ks < 2; ks++) {
            uint32_t ah[4][4], bh[4][2], bl[4][2];
            {
                const int kk = ks * 16 + (lane >> 4) * 8;
                #pragma unroll
                for (int mt = 0; mt < 4; mt++) {
                    const int ra = wm * 64 + mt * 16 + (lane & 15);
                    LDSM4(ah[mt], stg + ra * 80 + kk * 2);
                }
            }
            {
                const int kk = ks * 16 + ((lane >> 3) & 1) * 8;
                #pragma unroll
                for (int nt = 0; nt < 4; nt++) {
                    const int rb = wn * 32 + nt * 8 + (lane & 7);
                    uint32_t bd = stg + TILE_BYTES + rb * 80 + kk * 2;
                    LDSM2(bh[nt], bd);
                    LDSM2(bl[nt], bd + TILE_BYTES);
                }
            }
            #pragma unroll
            for (int mt = 0; mt < 4; mt++)
                #pragma unroll
                for (int nt = 0; nt < 4; nt++) {
                    MMA_F16(acc[mt][nt], ah[mt], bh[nt]);
                    MMA_F16(acc[mt][nt], ah[mt], bl[nt]);
                }
        }
        __syncthreads();
    }

    const int g = lane >> 2, th = lane & 3;
    #pragma unroll
    for (int mt = 0; mt < 4; mt++)
        #pragma unroll
        for (int nt = 0; nt < 4; nt++) {
            const int row = row0 + wm * 64 + mt * 16 + g;
            const int col = col0 + wn * 32 + nt * 8 + th * 2;
            float2 bv = make_float2(0.f, 0.f);
            if (p.mode == 0) bv = *(const float2*)(p.bias + col);
            const float* cc = acc[mt][nt];
            #pragma unroll
            for (int h = 0; h < 2; h++) {
                float v0 = cc[h * 2 + 0] + bv.x;
                float v1 = cc[h * 2 + 1] + bv.y;
                size_t o = (size_t)(row + h * 8) * CDIM + col;
                if (p.mode == 3) {
                    *(float2*)(p.oF + o) = make_float2(v0, v1);
                } else {
                    if (p.mode == 0) { v0 = fmaxf(v0, 0.f); v1 = fmaxf(v1, 0.f); }
                    *(uint32_t*)(p.oH + o) = hf2pk(v1, v0);
                }
            }
        }
}

// ============================================================================
// split-K combine: X = fp16split(P0 + P1 + bias)
// ============================================================================
__global__ __launch_bounds__(256)
void combine_kernel(const float* __restrict__ P0, const float* __restrict__ P1,
                    const float* __restrict__ bias,
                    __half* __restrict__ hi, __half* __restrict__ lo) {
    int i = blockIdx.x * blockDim.x + threadIdx.x;      // float4 index
    float4 a = ((const float4*)P0)[i];
    float4 b = ((const float4*)P1)[i];
    int col = (i & (CDIM / 4 - 1)) * 4;
    float4 bv = *(const float4*)(bias + col);
    float f[4] = {a.x + b.x + bv.x, a.y + b.y + bv.y,
                  a.z + b.z + bv.z, a.w + b.w + bv.w};
    uint32_t hu[2], lu[2];
    #pragma unroll
    for (int j = 0; j < 2; j++) {
        uint32_t h = hf2pk(f[2*j+1], f[2*j]);
        __half2 hh = *(__half2*)&h;
        float2 e = __half22float2(hh);
        hu[j] = h;
        lu[j] = hf2pk(f[2*j+1] - e.y, f[2*j] - e.x);
    }
    ((uint2*)hi)[i] = make_uint2(hu[0], hu[1]);
    ((uint2*)lo)[i] = make_uint2(lu[0], lu[1]);
}

// ============================================================================
// HMMA flash attention — fp16 2-MMA S phase (Q = Xh only, K = Xh+Xl),
// single-fp16 V (2-MMA O phase). 72KB smem. [R14 proven, unchanged]
// ============================================================================
#define FP 144
#define SOFF(s, t)  (128 * FP + (s) * (3 * 64 * FP) + (t) * (64 * FP))
#define FLASH_SMEM  (128 * FP + 2 * 3 * 64 * FP)       // 73728 B
#define SCL8_LOG2E  0.1803368801111204f                 // 0.125 * log2(e)

__global__ __launch_bounds__(256)
void flash_hmma(const __half* __restrict__ Xh, const __half* __restrict__ Xl,
                const __half* __restrict__ Vh,
                const float* __restrict__ LI, const float* __restrict__ bout,
                float* __restrict__ out) {
    extern __shared__ char smc[];
    const uint32_t sb = smem_u32(smc);
    const int tid = threadIdx.x;
    const int wid = tid >> 5, lane = tid & 31;
    const int g = lane >> 2, th = lane & 3;
    const int n0 = blockIdx.x * 128;
    const int grp = blockIdx.y;
    const size_t gcol = (size_t)grp * DH;

    const void* kvsrc[3] = {Xh, Xl, Vh};

    #pragma unroll
    for (int i = 0; i < 4; i++) {
        int id = tid + i * 256;
        int r = id >> 3, q = id & 7;
        const char* src = (const char*)(Xh + (size_t)(n0 + r) * CDIM + gcol) + q * 16;
        CP16(sb + r * FP + q * 16, src);
    }
    auto cp_kv = [&](int it, int s) {
        const int m0 = it * 64;
        #pragma unroll
        for (int i = 0; i < 6; i++) {
            int id = tid + i * 256;
            int t = id >> 9, rem = id & 511;
            int r = rem >> 3, q = rem & 7;
            uint32_t dst = sb + SOFF(s, t) + r * FP + q * 16;
            const char* src = (const char*)kvsrc[t] + ((size_t)(m0 + r) * CDIM + gcol) * 2 + q * 16;
            CP16(dst, src);
        }
    };

    cp_kv(0, 0);
    CP_COMMIT();
    CP_WAIT(0);
    __syncthreads();

    uint32_t qa[4][4];
    #pragma unroll
    for (int kt = 0; kt < 4; kt++) {
        uint32_t ad = sb + (wid * 16 + (lane & 15)) * FP
                    + (kt * 16 + (lane >> 4) * 8) * 2;
        LDSM4(qa[kt], ad);
    }

    float accO[8][4] = {};
    float mi0 = -CUDART_INF_F, mi1 = -CUDART_INF_F;
    float ls0 = 0.f, ls1 = 0.f;

    const float* lbase = LI + (size_t)(n0 + wid * 16 + g) * NROI + 2 * th;

    for (int it = 0; it < 32; it++) {
        const int s = it & 1;

        float2 liA[8], liB[8];
        {
            const float* lp = lbase + it * 64;
            #pragma unroll
            for (int nt = 0; nt < 8; nt++) {
                liA[nt] = *(const float2*)(lp + nt * 8);
                liB[nt] = *(const float2*)(lp + 8 * NROI + nt * 8);
            }
        }

        if (it < 31) { cp_kv(it + 1, s ^ 1); CP_COMMIT(); CP_WAIT(1); }
        else         { CP_WAIT(0); }
        __syncthreads();

        const uint32_t stK = sb + SOFF(s, 0);
        const uint32_t stV = sb + SOFF(s, 2);

        float accS[8][4] = {};
        #pragma unroll
        for (int kt = 0; kt < 4; kt++) {
            uint32_t kh[4][4], kl[4][4];
            #pragma unroll
            for (int p = 0; p < 4; p++) {
                uint32_t ad = stK + (p * 16 + (lane & 15)) * FP
                            + (kt * 16 + (lane >> 4) * 8) * 2;
                LDSM4(kh[p], ad);
                LDSM4(kl[p], ad + 64 * FP);
            }
            #pragma unroll
            for (int p = 0; p < 4; p++) {
                uint32_t b0h[2] = {kh[p][0], kh[p][2]}, b1h[2] = {kh[p][1], kh[p][3]};
                uint32_t b0l[2] = {kl[p][0], kl[p][2]}, b1l[2] = {kl[p][1], kl[p][3]};
                MMA_F16(accS[2*p],   qa[kt], b0h);
                MMA_F16(accS[2*p],   qa[kt], b0l);
                MMA_F16(accS[2*p+1], qa[kt], b1h);
                MMA_F16(accS[2*p+1], qa[kt], b1l);
            }
        }

        #pragma unroll
        for (int nt = 0; nt < 8; nt++) {
            accS[nt][0] = fmaf(accS[nt][0], SCL8_LOG2E, liA[nt].x);
            accS[nt][1] = fmaf(accS[nt][1], SCL8_LOG2E, liA[nt].y);
            accS[nt][2] = fmaf(accS[nt][2], SCL8_LOG2E, liB[nt].x);
            accS[nt][3] = fmaf(accS[nt][3], SCL8_LOG2E, liB[nt].y);
        }

        float mt0 = -CUDART_INF_F, mt1 = -CUDART_INF_F;
        #pragma unroll
        for (int nt = 0; nt < 8; nt++) {
            mt0 = fmaxf(mt0, fmaxf(accS[nt][0], accS[nt][1]));
            mt1 = fmaxf(mt1, fmaxf(accS[nt][2], accS[nt][3]));
        }
        mt0 = fmaxf(mt0, __shfl_xor_sync(0xffffffffu, mt0, 1));
        mt0 = fmaxf(mt0, __shfl_xor_sync(0xffffffffu, mt0, 2));
        mt1 = fmaxf(mt1, __shfl_xor_sync(0xffffffffu, mt1, 1));
        mt1 = fmaxf(mt1, __shfl_xor_sync(0xffffffffu, mt1, 2));
        float mn0 = fmaxf(mi0, mt0), mn1 = fmaxf(mi1, mt1);
        float al0 = ex2f(mi0 - mn0), al1 = ex2f(mi1 - mn1);
        mi0 = mn0; mi1 = mn1;

        uint32_t pa[4][4];
        float rs0 = 0.f, rs1 = 0.f;
        #pragma unroll
        for (int nt = 0; nt < 8; nt++) {
            float p0 = ex2f(accS[nt][0] - mn0 + 10.f);
            float p1 = ex2f(accS[nt][1] - mn0 + 10.f);
            float p2 = ex2f(accS[nt][2] - mn1 + 10.f);
            float p3 = ex2f(accS[nt][3] - mn1 + 10.f);
            rs0 += p0 + p1; rs1 += p2 + p3;
            int kt = nt >> 1, off = (nt & 1) * 2;
            pa[kt][off]     = hf2pk(p1, p0);
            pa[kt][off + 1] = hf2pk(p3, p2);
        }
        rs0 += __shfl_xor_sync(0xffffffffu, rs0, 1);
        rs0 += __shfl_xor_sync(0xffffffffu, rs0, 2);
        rs1 += __shfl_xor_sync(0xffffffffu, rs1, 1);
        rs1 += __shfl_xor_sync(0xffffffffu, rs1, 2);
        ls0 = ls0 * al0 + rs0;
        ls1 = ls1 * al1 + rs1;

        #pragma unroll
        for (int nt = 0; nt < 8; nt++) {
            accO[nt][0] *= al0; accO[nt][1] *= al0;
            accO[nt][2] *= al1; accO[nt][3] *= al1;
        }

        #pragma unroll
        for (int kt = 0; kt < 4; kt++) {
            #pragma unroll
            for (int db = 0; db < 4; db++) {
                uint32_t vh[4];
                uint32_t ad = stV + (kt * 16 + (lane & 15)) * FP
                            + (db * 16 + (lane >> 4) * 8) * 2;
                LDSM4T(vh, ad);
                uint32_t bh0[2] = {vh[0], vh[1]}, bh1[2] = {vh[2], vh[3]};
                MMA_F16(accO[2*db],   pa[kt], bh0);
                MMA_F16(accO[2*db+1], pa[kt], bh1);
            }
        }
        __syncthreads();
    }

    const float inv0 = 1.f / ls0, inv1 = 1.f / ls1;
    #pragma unroll
    for (int nt = 0; nt < 8; nt++) {
        const int col = grp * DH + nt * 8 + 2 * th;
        float2 bo = *(const float2*)(bout + col);
        const int row = n0 + wid * 16 + g;
        *(float2*)(out + (size_t)row * CDIM + col) =
            make_float2(accO[nt][0] * inv0 + bo.x, accO[nt][1] * inv0 + bo.y);
        *(float2*)(out + (size_t)(row + 8) * CDIM + col) =
            make_float2(accO[nt][2] * inv1 + bo.x, accO[nt][3] * inv1 + bo.y);
    }
}

// ============================================================================
// launch
// ============================================================================
extern "C" void kernel_launch(void* const* d_in, const int* in_sizes, int n_in,
                              void* d_out, int out_size) {
    const float* in_x = (const float*)d_in[0];
    const float* rois = (const float*)d_in[1];
    const float* W0   = (const float*)d_in[2];
    const float* b0   = (const float*)d_in[3];
    const float* W1   = (const float*)d_in[4];
    const float* b1   = (const float*)d_in[5];
    const float* Wout = (const float*)d_in[6];
    const float* bout = (const float*)d_in[7];
    float* out = (float*)d_out;

    void *pA0,*pA1,*pA2,*pW0h,*pW0l,*pW1h,*pW1l,*pWph,*pWpl;
    void *pXh,*pXl,*pVh,*pLI,*pPt0,*pPt1;
    cudaGetSymbolAddress(&pA0, g_A0);
    cudaGetSymbolAddress(&pA1, g_A1);
    cudaGetSymbolAddress(&pA2, g_A2);
    cudaGetSymbolAddress(&pW0h, g_W0h); cudaGetSymbolAddress(&pW0l, g_W0l);
    cudaGetSymbolAddress(&pW1h, g_W1h); cudaGetSymbolAddress(&pW1l, g_W1l);
    cudaGetSymbolAddress(&pWph, g_Wph); cudaGetSymbolAddress(&pWpl, g_Wpl);
    cudaGetSymbolAddress(&pXh, g_Xh);   cudaGetSymbolAddress(&pXl, g_Xl);
    cudaGetSymbolAddress(&pVh, g_Vh);
    cudaGetSymbolAddress(&pPt0, g_Pt0); cudaGetSymbolAddress(&pPt1, g_Pt1);
    cudaGetSymbolAddress(&pLI, g_LI);

    // merged prep (activations fp16 single, weights fp16 hi/lo, logiou)
    prep_all<<<7168 + 16384, 256>>>(in_x, W0, W1, Wout, rois, (float*)pLI,
                                    (__half*)pA0, (__half*)pA2,
                                    (__half*)pW0h, (__half*)pW0l,
                                    (__half*)pW1h, (__half*)pW1l,
                                    (__half*)pWph, (__half*)pWpl);

    cudaFuncSetAttribute(gemm_tc, cudaFuncAttributeMaxDynamicSharedMemorySize, GEMM_SMEM);

    // GEMM0 (mode0) ∥ GEMM2 (mode2): 256 CTAs, one co-resident wave
    GP g0 = {(__half*)pA0, (__half*)pW0h, (__half*)pW0l,
             b0, (__half*)pA1, nullptr, 0, 32, 0};
    GP g2 = {(__half*)pA2, (__half*)pWph, (__half*)pWpl,
             nullptr, (__half*)pVh, nullptr, 0, 32, 2};
    gemm_tc<<<dim3(CDIM / 128, NROI / 128, 2), 256, GEMM_SMEM>>>(g0, g2);

    // GEMM1 split-K=2 (mode3 partials): 256 CTAs, one wave
    GP g1a = {(__half*)pA1, (__half*)pW1h, (__half*)pW1l,
              nullptr, nullptr, (float*)pPt0, 0, 16, 3};
    GP g1b = {(__half*)pA1, (__half*)pW1h, (__half*)pW1l,
              nullptr, nullptr, (float*)pPt1, 16, 16, 3};
    gemm_tc<<<dim3(CDIM / 128, NROI / 128, 2), 256, GEMM_SMEM>>>(g1a, g1b);

    // combine partials -> X (fp16 split)
    combine_kernel<<<(NROI * CDIM / 4) / 256, 256>>>((float*)pPt0, (float*)pPt1, b1,
                                                     (__half*)pXh, (__half*)pXl);

    // HMMA flash attention (unchanged from R14)
    cudaFuncSetAttribute(flash_hmma, cudaFuncAttributeMaxDynamicSharedMemorySize, FLASH_SMEM);
    flash_hmma<<<dim3(NROI / 128, GRP), 256, FLASH_SMEM>>>(
        (__half*)pXh, (__half*)pXl,
        (__half*)pVh, (float*)pLI, bout, out);
}

// round 17
// speedup vs baseline: 2.2425x; 1.0418x over previous
#include <cuda_runtime.h>
#include <cuda_bf16.h>
#include <cuda_fp16.h>
#include <math_constants.h>
#include <cstdint>

#define NROI 2048
#define CDIM 1024
#define GRP  16
#define DH   64

// ============================================================================
// device scratch
// ============================================================================
__device__ __half g_A0[NROI * CDIM];                    // relu(in_x), fp16 single
__device__ __half g_A1[NROI * CDIM];                    // relu(H0), fp16 single
__device__ __half g_A2[NROI * CDIM];                    // in_x, fp16 single
__device__ __half g_W0h[CDIM * CDIM], g_W0l[CDIM * CDIM];   // weights, fp16 hi/lo
__device__ __half g_W1h[CDIM * CDIM], g_W1l[CDIM * CDIM];
__device__ __half g_Wph[CDIM * CDIM], g_Wpl[CDIM * CDIM];
__device__ __half g_X[NROI * CDIM];                     // embedded X (Q/K), fp16 single
__device__ __half g_Vh[NROI * CDIM];                    // V, single fp16
__device__ float g_Pt0[NROI * CDIM], g_Pt1[NROI * CDIM];// split-K partials (GEMM1)
__device__ float g_LI[NROI * NROI];                     // log2(iou + 1e-6)

// ============================================================================
// PTX helpers
// ============================================================================
__device__ __forceinline__ uint32_t smem_u32(const void* p) {
    uint32_t a;
    asm("{ .reg .u64 t; cvta.to.shared.u64 t, %1; cvt.u32.u64 %0, t; }" : "=r"(a) : "l"(p));
    return a;
}
#define LDSM4(r, addr) \
    asm volatile("ldmatrix.sync.aligned.m8n8.x4.shared.b16 {%0,%1,%2,%3}, [%4];" \
        : "=r"((r)[0]), "=r"((r)[1]), "=r"((r)[2]), "=r"((r)[3]) : "r"(addr))
#define LDSM4T(r, addr) \
    asm volatile("ldmatrix.sync.aligned.m8n8.x4.trans.shared.b16 {%0,%1,%2,%3}, [%4];" \
        : "=r"((r)[0]), "=r"((r)[1]), "=r"((r)[2]), "=r"((r)[3]) : "r"(addr))
#define LDSM2(r, addr) \
    asm volatile("ldmatrix.sync.aligned.m8n8.x2.shared.b16 {%0,%1}, [%2];" \
        : "=r"((r)[0]), "=r"((r)[1]) : "r"(addr))
#define MMA_F16(c, a, b) \
    asm volatile("mma.sync.aligned.m16n8k16.row.col.f32.f16.f16.f32 " \
        "{%0,%1,%2,%3}, {%4,%5,%6,%7}, {%8,%9}, {%0,%1,%2,%3};" \
        : "+f"((c)[0]), "+f"((c)[1]), "+f"((c)[2]), "+f"((c)[3]) \
        : "r"((a)[0]), "r"((a)[1]), "r"((a)[2]), "r"((a)[3]), "r"((b)[0]), "r"((b)[1]))
#define CP16(dst, src)  asm volatile("cp.async.cg.shared.global [%0], [%1], 16;" :: "r"(dst), "l"(src))
#define CP_COMMIT()     asm volatile("cp.async.commit_group;" ::: "memory")
#define CP_WAIT(n)      asm volatile("cp.async.wait_group %0;" :: "n"(n) : "memory")

__device__ __forceinline__ uint32_t hf2pk(float hi, float lo) {
    uint32_t r; asm("cvt.rn.f16x2.f32 %0, %1, %2;" : "=r"(r) : "f"(hi), "f"(lo)); return r;
}
__device__ __forceinline__ float ex2f(float x) {
    float r; asm("ex2.approx.f32 %0, %1;" : "=f"(r) : "f"(x)); return r;
}

// ============================================================================
// merged prep kernel: activations -> fp16 single, weights -> fp16 hi/lo,
// plus log2-IoU table; one launch
// ============================================================================
__global__ __launch_bounds__(256)
void prep_all(const float* __restrict__ in_x, const float* __restrict__ W0,
              const float* __restrict__ W1, const float* __restrict__ Wp,
              const float* __restrict__ rois, float* __restrict__ li,
              __half* __restrict__ a0, __half* __restrict__ a2,
              __half* __restrict__ w0h, __half* __restrict__ w0l,
              __half* __restrict__ w1h, __half* __restrict__ w1l,
              __half* __restrict__ wph, __half* __restrict__ wpl) {
    const int b = blockIdx.x;
    if (b >= 7168) {                       // ---- log-IoU segment ----
        int idx = (b - 7168) * 256 + threadIdx.x;
        int n = idx >> 11;
        int m = idx & 2047;
        const float* a = rois + n * 5 + 1;
        const float* bb = rois + m * 5 + 1;
        float ax1 = a[0], ay1 = a[1], ax2 = a[2], ay2 = a[3];
        float bx1 = bb[0], by1 = bb[1], bx2 = bb[2], by2 = bb[3];
        float areaA = (ax2 - ax1 + 1.f) * (ay2 - ay1 + 1.f);
        float areaB = (bx2 - bx1 + 1.f) * (by2 - by1 + 1.f);
        float w = fminf(ax2, bx2) - fmaxf(ax1, bx1) + 1.f; w = fmaxf(w, 0.f);
        float h = fminf(ay2, by2) - fmaxf(ay1, by1) + 1.f; h = fmaxf(h, 0.f);
        float inter = w * h;
        float iou = __fdividef(inter, areaA + areaB - inter);
        li[idx] = __log2f(iou + 1e-6f);
        return;
    }
    if (b < 4096) {                        // ---- activations: fp16 single ----
        const float* src = in_x;
        __half* dst = (b < 2048) ? a0 : a2;
        int relu = (b < 2048);
        int i = (b & 2047) * 256 + threadIdx.x;
        float4 v = ((const float4*)src)[i];
        if (relu) {
            v.x = fmaxf(v.x, 0.f); v.y = fmaxf(v.y, 0.f);
            v.z = fmaxf(v.z, 0.f); v.w = fmaxf(v.w, 0.f);
        }
        ((uint2*)dst)[i] = make_uint2(hf2pk(v.y, v.x), hf2pk(v.w, v.z));
        return;
    }
    // ---- weights: fp16 hi/lo split ----
    const float* src; __half *hi, *lo; int base;
    if      (b < 5120) { src = W0; hi = w0h; lo = w0l; base = 4096; }
    else if (b < 6144) { src = W1; hi = w1h; lo = w1l; base = 5120; }
    else               { src = Wp; hi = wph; lo = wpl; base = 6144; }
    int i = (b - base) * 256 + threadIdx.x;
    float4 v = ((const float4*)src)[i];
    float f[4] = {v.x, v.y, v.z, v.w};
    uint32_t hu[2], lu[2];
    #pragma unroll
    for (int j = 0; j < 2; j++) {
        uint32_t h = hf2pk(f[2*j+1], f[2*j]);
        __half2 hh = *(__half2*)&h;
        float2 e = __half22float2(hh);
        hu[j] = h;
        lu[j] = hf2pk(f[2*j+1] - e.y, f[2*j] - e.x);
    }
    ((uint2*)hi)[i] = make_uint2(hu[0], hu[1]);
    ((uint2*)lo)[i] = make_uint2(lu[0], lu[1]);
}

// ============================================================================
// HMMA fp16 2-MMA GEMM, 128x128 tile, dual-problem via gridDim.z
//   acc = A (Bh + Bl)^T;  A single fp16, B fp16 hi/lo
//   mode 0: relu(acc+bias) -> fp16     mode 2: acc -> fp16
//   mode 3: acc -> fp32 partial (split-K)
// ============================================================================
struct GP {
    const __half *A, *Bh, *Bl;
    const float* bias;
    __half* oH;
    float* oF;
    int kStart, nChunks, mode;
};

#define TILE_BYTES  10240            // 128 rows x 80 B
#define STAGE_BYTES (3 * TILE_BYTES) // A, Bh, Bl
#define GEMM_SMEM   (2 * STAGE_BYTES)  // 61440

__global__ __launch_bounds__(256, 2)
void gemm_tc(GP p0, GP p1) {
    const GP p = (blockIdx.z == 0) ? p0 : p1;
    extern __shared__ char smc[];
    const uint32_t sb = smem_u32(smc);
    const int tid = threadIdx.x;
    const int wid = tid >> 5, lane = tid & 31;
    const int wm = wid & 1, wn = wid >> 1;
    const int row0 = blockIdx.y * 128;
    const int col0 = blockIdx.x * 128;

    const __half* srcs[3] = {p.A, p.Bh, p.Bl};

    auto cp_chunk = [&](int c, int s) {
        const int kb = (p.kStart + c) * 32;
        #pragma unroll
        for (int i = 0; i < 6; i++) {
            int id = tid + i * 256;                    // 0..1535
            int t = id >> 9, rem = id & 511;
            int r = rem >> 2, q = rem & 3;
            const char* src = (const char*)(srcs[t] + (size_t)((t == 0 ? row0 : col0) + r) * CDIM + kb) + q * 16;
            CP16(sb + s * STAGE_BYTES + t * TILE_BYTES + r * 80 + q * 16, src);
        }
    };

    float acc[4][4][4] = {};
    cp_chunk(0, 0); CP_COMMIT();

    const int NC = p.nChunks;
    for (int c = 0; c < NC; c++) {
        const int s = c & 1;
        if (c < NC - 1) { cp_chunk(c + 1, s ^ 1); CP_COMMIT(); CP_WAIT(1); }
        else            { CP_WAIT(0); }
        __syncthreads();

        const uint32_t stg = sb + s * STAGE_BYTES;
        #pragma unroll
        for (int ks = 0; ks < 2; ks++) {
            uint32_t ah[4][4], bh[4][2], bl[4][2];
            {
                const int kk = ks * 16 + (lane >> 4) * 8;
                #pragma unroll
                for (int mt = 0; mt < 4; mt++) {
                    const int ra = wm * 64 + mt * 16 + (lane & 15);
                    LDSM4(ah[mt], stg + ra * 80 + kk * 2);
                }
            }
            {
                const int kk = ks * 16 + ((lane >> 3) & 1) * 8;
                #pragma unroll
                for (int nt = 0; nt < 4; nt++) {
                    const int rb = wn * 32 + nt * 8 + (lane & 7);
                    uint32_t bd = stg + TILE_BYTES + rb * 80 + kk * 2;
                    LDSM2(bh[nt], bd);
                    LDSM2(bl[nt], bd + TILE_BYTES);
                }
            }
            #pragma unroll
            for (int mt = 0; mt < 4; mt++)
                #pragma unroll
                for (int nt = 0; nt < 4; nt++) {
                    MMA_F16(acc[mt][nt], ah[mt], bh[nt]);
                    MMA_F16(acc[mt][nt], ah[mt], bl[nt]);
                }
        }
        __syncthreads();
    }

    const int g = lane >> 2, th = lane & 3;
    #pragma unroll
    for (int mt = 0; mt < 4; mt++)
        #pragma unroll
        for (int nt = 0; nt < 4; nt++) {
            const int row = row0 + wm * 64 + mt * 16 + g;
            const int col = col0 + wn * 32 + nt * 8 + th * 2;
            float2 bv = make_float2(0.f, 0.f);
            if (p.mode == 0) bv = *(const float2*)(p.bias + col);
            const float* cc = acc[mt][nt];
            #pragma unroll
            for (int h = 0; h < 2; h++) {
                float v0 = cc[h * 2 + 0] + bv.x;
                float v1 = cc[h * 2 + 1] + bv.y;
                size_t o = (size_t)(row + h * 8) * CDIM + col;
                if (p.mode == 3) {
                    *(float2*)(p.oF + o) = make_float2(v0, v1);
                } else {
                    if (p.mode == 0) { v0 = fmaxf(v0, 0.f); v1 = fmaxf(v1, 0.f); }
                    *(uint32_t*)(p.oH + o) = hf2pk(v1, v0);
                }
            }
        }
}

// ============================================================================
// split-K combine: X = fp16(P0 + P1 + bias)  (single fp16 now)
// ============================================================================
__global__ __launch_bounds__(256)
void combine_kernel(const float* __restrict__ P0, const float* __restrict__ P1,
                    const float* __restrict__ bias,
                    __half* __restrict__ outh) {
    int i = blockIdx.x * blockDim.x + threadIdx.x;      // float4 index
    float4 a = ((const float4*)P0)[i];
    float4 b = ((const float4*)P1)[i];
    int col = (i & (CDIM / 4 - 1)) * 4;
    float4 bv = *(const float4*)(bias + col);
    ((uint2*)outh)[i] = make_uint2(
        hf2pk(a.y + b.y + bv.y, a.x + b.x + bv.x),
        hf2pk(a.w + b.w + bv.w, a.z + b.z + bv.z));
}

// ============================================================================
// HMMA flash attention — single-fp16 Q/K (1-MMA S phase) and V (1-MMA O phase)
// 64 MMAs/warp/iter, 54KB smem
// ============================================================================
#define FP 144
#define SOFF(s, t)  (128 * FP + (s) * (2 * 64 * FP) + (t) * (64 * FP))
#define FLASH_SMEM  (128 * FP + 2 * 2 * 64 * FP)       // 55296 B
#define SCL8_LOG2E  0.1803368801111204f                 // 0.125 * log2(e)

__global__ __launch_bounds__(256)
void flash_hmma(const __half* __restrict__ X, const __half* __restrict__ Vh,
                const float* __restrict__ LI, const float* __restrict__ bout,
                float* __restrict__ out) {
    extern __shared__ char smc[];
    const uint32_t sb = smem_u32(smc);
    const int tid = threadIdx.x;
    const int wid = tid >> 5, lane = tid & 31;
    const int g = lane >> 2, th = lane & 3;
    const int n0 = blockIdx.x * 128;
    const int grp = blockIdx.y;
    const size_t gcol = (size_t)grp * DH;

    const void* kvsrc[2] = {X, Vh};

    // ---- cp.async: Q (128x64 fp16) once ----
    #pragma unroll
    for (int i = 0; i < 4; i++) {
        int id = tid + i * 256;
        int r = id >> 3, q = id & 7;
        const char* src = (const char*)(X + (size_t)(n0 + r) * CDIM + gcol) + q * 16;
        CP16(sb + r * FP + q * 16, src);
    }
    auto cp_kv = [&](int it, int s) {
        const int m0 = it * 64;
        #pragma unroll
        for (int i = 0; i < 4; i++) {
            int id = tid + i * 256;                     // 0..1023
            int t = id >> 9, rem = id & 511;
            int r = rem >> 3, q = rem & 7;
            uint32_t dst = sb + SOFF(s, t) + r * FP + q * 16;
            const char* src = (const char*)kvsrc[t] + ((size_t)(m0 + r) * CDIM + gcol) * 2 + q * 16;
            CP16(dst, src);
        }
    };

    cp_kv(0, 0);
    CP_COMMIT();
    CP_WAIT(0);
    __syncthreads();

    // ---- Q fragments resident for all iterations ----
    uint32_t qa[4][4];
    #pragma unroll
    for (int kt = 0; kt < 4; kt++) {
        uint32_t ad = sb + (wid * 16 + (lane & 15)) * FP
                    + (kt * 16 + (lane >> 4) * 8) * 2;
        LDSM4(qa[kt], ad);
    }

    float accO[8][4] = {};
    float mi0 = -CUDART_INF_F, mi1 = -CUDART_INF_F;
    float ls0 = 0.f, ls1 = 0.f;

    const float* lbase = LI + (size_t)(n0 + wid * 16 + g) * NROI + 2 * th;

    for (int it = 0; it < 32; it++) {
        const int s = it & 1;

        float2 liA[8], liB[8];
        {
            const float* lp = lbase + it * 64;
            #pragma unroll
            for (int nt = 0; nt < 8; nt++) {
                liA[nt] = *(const float2*)(lp + nt * 8);
                liB[nt] = *(const float2*)(lp + 8 * NROI + nt * 8);
            }
        }

        if (it < 31) { cp_kv(it + 1, s ^ 1); CP_COMMIT(); CP_WAIT(1); }
        else         { CP_WAIT(0); }
        __syncthreads();

        const uint32_t stK = sb + SOFF(s, 0);
        const uint32_t stV = sb + SOFF(s, 1);

        // ---- S = Qh Kh^T : 1 fp16 MMA per 16x16 block ----
        float accS[8][4] = {};
        #pragma unroll
        for (int kt = 0; kt < 4; kt++) {
            uint32_t kh[4][4];
            #pragma unroll
            for (int p = 0; p < 4; p++) {
                uint32_t ad = stK + (p * 16 + (lane & 15)) * FP
                            + (kt * 16 + (lane >> 4) * 8) * 2;
                LDSM4(kh[p], ad);
            }
            #pragma unroll
            for (int p = 0; p < 4; p++) {
                uint32_t b0h[2] = {kh[p][0], kh[p][2]}, b1h[2] = {kh[p][1], kh[p][3]};
                MMA_F16(accS[2*p],   qa[kt], b0h);
                MMA_F16(accS[2*p+1], qa[kt], b1h);
            }
        }

        #pragma unroll
        for (int nt = 0; nt < 8; nt++) {
            accS[nt][0] = fmaf(accS[nt][0], SCL8_LOG2E, liA[nt].x);
            accS[nt][1] = fmaf(accS[nt][1], SCL8_LOG2E, liA[nt].y);
            accS[nt][2] = fmaf(accS[nt][2], SCL8_LOG2E, liB[nt].x);
            accS[nt][3] = fmaf(accS[nt][3], SCL8_LOG2E, liB[nt].y);
        }

        float mt0 = -CUDART_INF_F, mt1 = -CUDART_INF_F;
        #pragma unroll
        for (int nt = 0; nt < 8; nt++) {
            mt0 = fmaxf(mt0, fmaxf(accS[nt][0], accS[nt][1]));
            mt1 = fmaxf(mt1, fmaxf(accS[nt][2], accS[nt][3]));
        }
        mt0 = fmaxf(mt0, __shfl_xor_sync(0xffffffffu, mt0, 1));
        mt0 = fmaxf(mt0, __shfl_xor_sync(0xffffffffu, mt0, 2));
        mt1 = fmaxf(mt1, __shfl_xor_sync(0xffffffffu, mt1, 1));
        mt1 = fmaxf(mt1, __shfl_xor_sync(0xffffffffu, mt1, 2));
        float mn0 = fmaxf(mi0, mt0), mn1 = fmaxf(mi1, mt1);
        float al0 = ex2f(mi0 - mn0), al1 = ex2f(mi1 - mn1);
        mi0 = mn0; mi1 = mn1;

        uint32_t pa[4][4];
        float rs0 = 0.f, rs1 = 0.f;
        #pragma unroll
        for (int nt = 0; nt < 8; nt++) {
            float p0 = ex2f(accS[nt][0] - mn0 + 10.f);
            float p1 = ex2f(accS[nt][1] - mn0 + 10.f);
            float p2 = ex2f(accS[nt][2] - mn1 + 10.f);
            float p3 = ex2f(accS[nt][3] - mn1 + 10.f);
            rs0 += p0 + p1; rs1 += p2 + p3;
            int kt = nt >> 1, off = (nt & 1) * 2;
            pa[kt][off]     = hf2pk(p1, p0);
            pa[kt][off + 1] = hf2pk(p3, p2);
        }
        rs0 += __shfl_xor_sync(0xffffffffu, rs0, 1);
        rs0 += __shfl_xor_sync(0xffffffffu, rs0, 2);
        rs1 += __shfl_xor_sync(0xffffffffu, rs1, 1);
        rs1 += __shfl_xor_sync(0xffffffffu, rs1, 2);
        ls0 = ls0 * al0 + rs0;
        ls1 = ls1 * al1 + rs1;

        #pragma unroll
        for (int nt = 0; nt < 8; nt++) {
            accO[nt][0] *= al0; accO[nt][1] *= al0;
            accO[nt][2] *= al1; accO[nt][3] *= al1;
        }

        // ---- O += P V (single fp16 V) ----
        #pragma unroll
        for (int kt = 0; kt < 4; kt++) {
            #pragma unroll
            for (int db = 0; db < 4; db++) {
                uint32_t vh[4];
                uint32_t ad = stV + (kt * 16 + (lane & 15)) * FP
                            + (db * 16 + (lane >> 4) * 8) * 2;
                LDSM4T(vh, ad);
                uint32_t bh0[2] = {vh[0], vh[1]}, bh1[2] = {vh[2], vh[3]};
                MMA_F16(accO[2*db],   pa[kt], bh0);
                MMA_F16(accO[2*db+1], pa[kt], bh1);
            }
        }
        __syncthreads();
    }

    const float inv0 = 1.f / ls0, inv1 = 1.f / ls1;
    #pragma unroll
    for (int nt = 0; nt < 8; nt++) {
        const int col = grp * DH + nt * 8 + 2 * th;
        float2 bo = *(const float2*)(bout + col);
        const int row = n0 + wid * 16 + g;
        *(float2*)(out + (size_t)row * CDIM + col) =
            make_float2(accO[nt][0] * inv0 + bo.x, accO[nt][1] * inv0 + bo.y);
        *(float2*)(out + (size_t)(row + 8) * CDIM + col) =
            make_float2(accO[nt][2] * inv1 + bo.x, accO[nt][3] * inv1 + bo.y);
    }
}

// ============================================================================
// launch
// ============================================================================
extern "C" void kernel_launch(void* const* d_in, const int* in_sizes, int n_in,
                              void* d_out, int out_size) {
    const float* in_x = (const float*)d_in[0];
    const float* rois = (const float*)d_in[1];
    const float* W0   = (const float*)d_in[2];
    const float* b0   = (const float*)d_in[3];
    const float* W1   = (const float*)d_in[4];
    const float* b1   = (const float*)d_in[5];
    const float* Wout = (const float*)d_in[6];
    const float* bout = (const float*)d_in[7];
    float* out = (float*)d_out;

    void *pA0,*pA1,*pA2,*pW0h,*pW0l,*pW1h,*pW1l,*pWph,*pWpl;
    void *pX,*pVh,*pLI,*pPt0,*pPt1;
    cudaGetSymbolAddress(&pA0, g_A0);
    cudaGetSymbolAddress(&pA1, g_A1);
    cudaGetSymbolAddress(&pA2, g_A2);
    cudaGetSymbolAddress(&pW0h, g_W0h); cudaGetSymbolAddress(&pW0l, g_W0l);
    cudaGetSymbolAddress(&pW1h, g_W1h); cudaGetSymbolAddress(&pW1l, g_W1l);
    cudaGetSymbolAddress(&pWph, g_Wph); cudaGetSymbolAddress(&pWpl, g_Wpl);
    cudaGetSymbolAddress(&pX, g_X);
    cudaGetSymbolAddress(&pVh, g_Vh);
    cudaGetSymbolAddress(&pPt0, g_Pt0); cudaGetSymbolAddress(&pPt1, g_Pt1);
    cudaGetSymbolAddress(&pLI, g_LI);

    // merged prep (activations fp16 single, weights fp16 hi/lo, logiou)
    prep_all<<<7168 + 16384, 256>>>(in_x, W0, W1, Wout, rois, (float*)pLI,
                                    (__half*)pA0, (__half*)pA2,
                                    (__half*)pW0h, (__half*)pW0l,
                                    (__half*)pW1h, (__half*)pW1l,
                                    (__half*)pWph, (__half*)pWpl);

    cudaFuncSetAttribute(gemm_tc, cudaFuncAttributeMaxDynamicSharedMemorySize, GEMM_SMEM);

    // GEMM0 (mode0) ∥ GEMM2 (mode2): 256 CTAs, one co-resident wave
    GP g0 = {(__half*)pA0, (__half*)pW0h, (__half*)pW0l,
             b0, (__half*)pA1, nullptr, 0, 32, 0};
    GP g2 = {(__half*)pA2, (__half*)pWph, (__half*)pWpl,
             nullptr, (__half*)pVh, nullptr, 0, 32, 2};
    gemm_tc<<<dim3(CDIM / 128, NROI / 128, 2), 256, GEMM_SMEM>>>(g0, g2);

    // GEMM1 split-K=2 (mode3 partials): 256 CTAs, one wave
    GP g1a = {(__half*)pA1, (__half*)pW1h, (__half*)pW1l,
              nullptr, nullptr, (float*)pPt0, 0, 16, 3};
    GP g1b = {(__half*)pA1, (__half*)pW1h, (__half*)pW1l,
              nullptr, nullptr, (float*)pPt1, 16, 16, 3};
    gemm_tc<<<dim3(CDIM / 128, NROI / 128, 2), 256, GEMM_SMEM>>>(g1a, g1b);

    // combine partials -> X (single fp16)
    combine_kernel<<<(NROI * CDIM / 4) / 256, 256>>>((float*)pPt0, (float*)pPt1, b1,
                                                     (__half*)pX);

    // HMMA flash attention (single-fp16 Q/K/V)
    cudaFuncSetAttribute(flash_hmma, cudaFuncAttributeMaxDynamicSharedMemorySize, FLASH_SMEM);
    flash_hmma<<<dim3(NROI / 128, GRP), 256, FLASH_SMEM>>>(
        (__half*)pX, (__half*)pVh, (float*)pLI, bout, out);
}